// round 1
// baseline (speedup 1.0000x reference)
#include <cuda_runtime.h>
#include <cstdint>
#include <cstddef>

#define D 128
#define N_BV 100000
#define N_LT 20000
#define N_CM 2000
#define N_DN 100000
#define E0_N 600000
#define E1_N 200000
#define E2_N 500000
#define E3_N 200000

// ---------------- scratch layout (floats) ----------------
constexpr size_t OF_AGG0 = 0;
constexpr size_t OF_AGG1 = OF_AGG0 + (size_t)N_BV * D;
constexpr size_t OF_AGG2 = OF_AGG1 + (size_t)N_BV * D;
constexpr size_t OF_AGG3 = OF_AGG2 + (size_t)N_LT * D;
constexpr size_t OF_AGG_END = OF_AGG3 + (size_t)N_CM * D;
constexpr size_t OF_CNT0 = OF_AGG_END;
constexpr size_t OF_CNT1 = OF_CNT0 + N_BV;
constexpr size_t OF_CNT2 = OF_CNT1 + N_BV;
constexpr size_t OF_CNT3 = OF_CNT2 + N_LT;
constexpr size_t OF_FTS0 = OF_CNT3 + N_CM;
constexpr size_t OF_FTS1 = OF_FTS0 + (size_t)N_BV * 16;
constexpr size_t OF_FTS2 = OF_FTS1 + (size_t)N_BV * 16;
constexpr size_t OF_FTS3 = OF_FTS2 + (size_t)N_LT * 16;
constexpr size_t OF_STAT_END = OF_FTS3 + (size_t)N_CM * 16;
constexpr size_t OF_H_BV = OF_STAT_END;
constexpr size_t OF_H_LT = OF_H_BV + (size_t)N_BV * D;
constexpr size_t OF_H_CM = OF_H_LT + (size_t)N_LT * D;
constexpr size_t OF_H_DN = OF_H_CM + (size_t)N_CM * D;
constexpr size_t OF_OUT_BV = OF_H_DN + (size_t)N_DN * D;
constexpr size_t OF_OUT_LT = OF_OUT_BV + (size_t)N_BV * D;
constexpr size_t OF_OUT_CM = OF_OUT_LT + (size_t)N_LT * D;
constexpr size_t OF_Z_LT = OF_OUT_CM + (size_t)N_CM * D;
constexpr size_t OF_Z_CM = OF_Z_LT + (size_t)N_LT * D;
constexpr size_t OF_BIAS_BV = OF_Z_CM + (size_t)N_CM * D;
constexpr size_t OF_BIAS_LT = OF_BIAS_BV + (size_t)N_BV * D;
constexpr size_t OF_BIAS_CM = OF_BIAS_LT + (size_t)N_LT * D;
constexpr size_t OF_WCOMB = OF_BIAS_CM + (size_t)N_CM * D;
constexpr size_t OF_BCOMB = OF_WCOMB + 2 * 128 * 128;
constexpr size_t SCRATCH_TOTAL = OF_BCOMB + 2 * 128;

__device__ __align__(128) float g_buf[SCRATCH_TOTAL];

// ---------------- helpers ----------------
__device__ __forceinline__ void red_add_v4(float* p, float4 v) {
    asm volatile("red.global.add.v4.f32 [%0], {%1, %2, %3, %4};"
                 :: "l"(p), "f"(v.x), "f"(v.y), "f"(v.z), "f"(v.w)
                 : "memory");
}

// ---------------- per-edge-type count + Time2Vec feature segment-sum (layer-invariant) ----------------
__global__ void cnt_ft_kernel(const int* __restrict__ dst, const float* __restrict__ ft,
                              float* __restrict__ cnt, float* __restrict__ fts, int E)
{
    int i = blockIdx.x * blockDim.x + threadIdx.x;
    if (i >= E) return;
    int d = dst[i];
    atomicAdd(cnt + d, 1.0f);
    const float4* f = reinterpret_cast<const float4*>(ft) + (size_t)i * 4;
    float* o = fts + (size_t)d * 16;
    red_add_v4(o + 0,  f[0]);
    red_add_v4(o + 4,  f[1]);
    red_add_v4(o + 8,  f[2]);
    red_add_v4(o + 12, f[3]);
}

// ---------------- edge-bias precompute: (seg_sum(ft)/c) @ emlpW + (c>0)*emlp_b ----------------
__global__ void bias_pre_kernel(const float* __restrict__ fts, const float* __restrict__ cnt,
                                const float* __restrict__ Wml, const float* __restrict__ bml,
                                float* __restrict__ out, int acc)
{
    int row = blockIdx.x;
    int c = threadIdx.x;
    __shared__ float f[16];
    if (c < 16) f[c] = fts[(size_t)row * 16 + c];
    __syncthreads();
    float cv = cnt[row];
    float inv = 1.0f / fmaxf(cv, 1.0f);
    float a = 0.0f;
#pragma unroll
    for (int j = 0; j < 16; j++) a = fmaf(f[j], Wml[j * 128 + c], a);
    a *= inv;
    if (cv > 0.0f) a += bml[c];
    size_t o = (size_t)row * 128 + c;
    if (acc) a += out[o];
    out[o] = a;
}

// ---------------- combine W_top of the two bv-targeting edge types ----------------
__global__ void wprep_kernel(const float* __restrict__ convW, const float* __restrict__ convB,
                             float* __restrict__ wcomb, float* __restrict__ bcomb)
{
    int idx = blockIdx.x * blockDim.x + threadIdx.x;
    if (idx < 2 * 128 * 128) {
        int l = idx >> 14;
        int rc = idx & 16383;
        wcomb[idx] = convW[(size_t)(l * 4 + 0) * 32768 + rc] +
                     convW[(size_t)(l * 4 + 1) * 32768 + rc];
    }
    if (idx < 256) {
        int l = idx >> 7, c = idx & 127;
        bcomb[idx] = convB[(l * 4 + 0) * 128 + c] + convB[(l * 4 + 1) * 128 + c];
    }
}

// ---------------- edge aggregation: warp per edge, gather 512B row, v4 reductions ----------------
__global__ void edge_agg_kernel(const int* __restrict__ src, const int* __restrict__ dst,
                                const float* __restrict__ X, float* __restrict__ agg, int E)
{
    int gw = (int)((blockIdx.x * blockDim.x + threadIdx.x) >> 5);
    int lane = threadIdx.x & 31;
    if (gw >= E) return;
    int s = __ldg(src + gw);
    int d = __ldg(dst + gw);
    float4 v = reinterpret_cast<const float4*>(X + (size_t)s * D)[lane];
    red_add_v4(agg + (size_t)d * D + (size_t)lane * 4, v);
}

// ---------------- fp32 GEMM: C[M,128] = A[M,128] @ W[128,128] (+bias)(+C)(row scaled by 1/max(cnt,1)) ----------------
__global__ __launch_bounds__(256) void gemm128_kernel(
    const float* __restrict__ A, int M,
    const float* __restrict__ W,
    const float* __restrict__ bias,
    const float* __restrict__ rowcnt,
    float* __restrict__ C, int accumulate)
{
    __shared__ float As[64][64];
    __shared__ float Ws[64][128];
    int tid = threadIdx.x;
    int row0 = blockIdx.x * 64;
    int tr = tid >> 4, tc = tid & 15;
    float acc[4][8];
#pragma unroll
    for (int i = 0; i < 4; i++)
#pragma unroll
        for (int j = 0; j < 8; j++) acc[i][j] = 0.0f;

    for (int k0 = 0; k0 < 128; k0 += 64) {
#pragma unroll
        for (int t = 0; t < 4; t++) {
            int i = tid + t * 256;
            int r = i >> 4;
            int c4 = i & 15;
            int gr = row0 + r;
            float4 v = make_float4(0.f, 0.f, 0.f, 0.f);
            if (gr < M) {
                v = *reinterpret_cast<const float4*>(A + (size_t)gr * 128 + k0 + c4 * 4);
                if (rowcnt) {
                    float sc = 1.0f / fmaxf(rowcnt[gr], 1.0f);
                    v.x *= sc; v.y *= sc; v.z *= sc; v.w *= sc;
                }
            }
            *reinterpret_cast<float4*>(&As[r][c4 * 4]) = v;
        }
#pragma unroll
        for (int t = 0; t < 8; t++) {
            int i = tid + t * 256;
            int r = i >> 5;
            int c4 = i & 31;
            *reinterpret_cast<float4*>(&Ws[r][c4 * 4]) =
                *reinterpret_cast<const float4*>(W + (size_t)(k0 + r) * 128 + c4 * 4);
        }
        __syncthreads();
#pragma unroll 8
        for (int k = 0; k < 64; k++) {
            float av[4];
#pragma unroll
            for (int i = 0; i < 4; i++) av[i] = As[tr * 4 + i][k];
            float4 b0 = *reinterpret_cast<const float4*>(&Ws[k][tc * 8]);
            float4 b1 = *reinterpret_cast<const float4*>(&Ws[k][tc * 8 + 4]);
            float bv8[8] = {b0.x, b0.y, b0.z, b0.w, b1.x, b1.y, b1.z, b1.w};
#pragma unroll
            for (int i = 0; i < 4; i++)
#pragma unroll
                for (int j = 0; j < 8; j++) acc[i][j] = fmaf(av[i], bv8[j], acc[i][j]);
        }
        __syncthreads();
    }
#pragma unroll
    for (int i = 0; i < 4; i++) {
        int gr = row0 + tr * 4 + i;
        if (gr >= M) continue;
        float* cp = C + (size_t)gr * 128 + tc * 8;
        float o[8];
#pragma unroll
        for (int j = 0; j < 8; j++) o[j] = acc[i][j];
        if (bias) {
#pragma unroll
            for (int j = 0; j < 8; j++) o[j] += bias[tc * 8 + j];
        }
        if (accumulate) {
            float4 p0 = *reinterpret_cast<const float4*>(cp);
            float4 p1 = *reinterpret_cast<const float4*>(cp + 4);
            o[0] += p0.x; o[1] += p0.y; o[2] += p0.z; o[3] += p0.w;
            o[4] += p1.x; o[5] += p1.y; o[6] += p1.z; o[7] += p1.w;
        }
        *reinterpret_cast<float4*>(cp)     = make_float4(o[0], o[1], o[2], o[3]);
        *reinterpret_cast<float4*>(cp + 4) = make_float4(o[4], o[5], o[6], o[7]);
    }
}

// ---------------- finish: add scaled aggregations + edge bias, then LayerNorm ----------------
__global__ void finish_ln_kernel(const float* __restrict__ outg,
                                 const float* __restrict__ aggA, const float* __restrict__ cntA,
                                 const float* __restrict__ aggB, const float* __restrict__ cntB,
                                 const float* __restrict__ biasadd,
                                 const float* __restrict__ g, const float* __restrict__ b,
                                 float* __restrict__ dest)
{
    int row = blockIdx.x, c = threadIdx.x;
    size_t o = (size_t)row * 128 + c;
    float v = outg[o];
    if (biasadd) v += biasadd[o];
    if (aggA) v += aggA[o] * (1.0f / fmaxf(cntA[row], 1.0f));
    if (aggB) v += aggB[o] * (1.0f / fmaxf(cntB[row], 1.0f));
    float s = v, s2 = v * v;
#pragma unroll
    for (int off = 16; off; off >>= 1) {
        s  += __shfl_xor_sync(0xffffffffu, s,  off);
        s2 += __shfl_xor_sync(0xffffffffu, s2, off);
    }
    __shared__ float ss[4], ss2[4];
    int w = c >> 5;
    if ((c & 31) == 0) { ss[w] = s; ss2[w] = s2; }
    __syncthreads();
    float tot  = ss[0]  + ss[1]  + ss[2]  + ss[3];
    float tot2 = ss2[0] + ss2[1] + ss2[2] + ss2[3];
    float m = tot * (1.0f / 128.0f);
    float var = tot2 * (1.0f / 128.0f) - m * m;
    dest[o] = (v - m) * rsqrtf(var + 1e-5f) * g[c] + b[c];
}

// ---------------- dn: LN(zeros) = ln_b broadcast ----------------
__global__ void fill_rows_kernel(float* __restrict__ dest, const float* __restrict__ b, size_t total)
{
    size_t i = (size_t)blockIdx.x * blockDim.x + threadIdx.x;
    if (i < total) dest[i] = b[i & 127];
}

// ---------------- launch ----------------
extern "C" void kernel_launch(void* const* d_in, const int* in_sizes, int n_in,
                              void* d_out, int out_size)
{
    (void)in_sizes; (void)n_in; (void)out_size;
    const float* h0_bv = (const float*)d_in[0];
    const float* h0_lt = (const float*)d_in[1];
    const float* h0_cm = (const float*)d_in[2];
    const float* h0_dn = (const float*)d_in[3];
    const float* ft0 = (const float*)d_in[4];
    const float* ft1 = (const float*)d_in[5];
    const float* ft2 = (const float*)d_in[6];
    const float* ft3 = (const float*)d_in[7];
    const float* convW = (const float*)d_in[8];
    const float* convB = (const float*)d_in[9];
    const float* emlpW = (const float*)d_in[10];
    const float* emlpB = (const float*)d_in[11];
    const float* lng = (const float*)d_in[12];
    const float* lnb = (const float*)d_in[13];
    const int* src0 = (const int*)d_in[14];
    const int* dst0 = (const int*)d_in[15];
    const int* src1 = (const int*)d_in[16];
    const int* dst1 = (const int*)d_in[17];
    const int* src2 = (const int*)d_in[18];
    const int* dst2 = (const int*)d_in[19];
    const int* src3 = (const int*)d_in[20];
    const int* dst3 = (const int*)d_in[21];
    float* out = (float*)d_out;

    float* buf = nullptr;
    cudaGetSymbolAddress((void**)&buf, g_buf);

    float* agg0 = buf + OF_AGG0;
    float* agg1 = buf + OF_AGG1;
    float* agg2 = buf + OF_AGG2;
    float* agg3 = buf + OF_AGG3;
    float* cnt0 = buf + OF_CNT0;
    float* cnt1 = buf + OF_CNT1;
    float* cnt2 = buf + OF_CNT2;
    float* cnt3 = buf + OF_CNT3;
    float* fts0 = buf + OF_FTS0;
    float* fts1 = buf + OF_FTS1;
    float* fts2 = buf + OF_FTS2;
    float* fts3 = buf + OF_FTS3;
    float* out_bv = buf + OF_OUT_BV;
    float* out_lt = buf + OF_OUT_LT;
    float* out_cm = buf + OF_OUT_CM;
    float* z_lt = buf + OF_Z_LT;
    float* z_cm = buf + OF_Z_CM;
    float* bias_bv = buf + OF_BIAS_BV;
    float* bias_lt = buf + OF_BIAS_LT;
    float* bias_cm = buf + OF_BIAS_CM;
    float* wcomb = buf + OF_WCOMB;
    float* bcomb = buf + OF_BCOMB;

    // ---- layer-invariant precompute ----
    cudaMemsetAsync(buf + OF_CNT0, 0, (OF_STAT_END - OF_CNT0) * sizeof(float), 0);
    cnt_ft_kernel<<<(E0_N + 255) / 256, 256>>>(dst0, ft0, cnt0, fts0, E0_N);
    cnt_ft_kernel<<<(E1_N + 255) / 256, 256>>>(dst1, ft1, cnt1, fts1, E1_N);
    cnt_ft_kernel<<<(E2_N + 255) / 256, 256>>>(dst2, ft2, cnt2, fts2, E2_N);
    cnt_ft_kernel<<<(E3_N + 255) / 256, 256>>>(dst3, ft3, cnt3, fts3, E3_N);

    bias_pre_kernel<<<N_BV, 128>>>(fts0, cnt0, emlpW + 0 * 2048, emlpB + 0,   bias_bv, 0);
    bias_pre_kernel<<<N_BV, 128>>>(fts1, cnt1, emlpW + 1 * 2048, emlpB + 128, bias_bv, 1);
    bias_pre_kernel<<<N_LT, 128>>>(fts2, cnt2, emlpW + 2 * 2048, emlpB + 256, bias_lt, 0);
    bias_pre_kernel<<<N_CM, 128>>>(fts3, cnt3, emlpW + 3 * 2048, emlpB + 384, bias_cm, 0);

    wprep_kernel<<<(2 * 128 * 128 + 255) / 256, 256>>>(convW, convB, wcomb, bcomb);

    for (int l = 0; l < 2; l++) {
        const float* cur_bv = (l == 0) ? h0_bv : buf + OF_H_BV;
        const float* cur_lt = (l == 0) ? h0_lt : buf + OF_H_LT;
        const float* cur_cm = (l == 0) ? h0_cm : buf + OF_H_CM;
        const float* cur_dn = (l == 0) ? h0_dn : buf + OF_H_DN;
        float* dst_bv = (l == 0) ? buf + OF_H_BV : out;
        float* dst_lt = (l == 0) ? buf + OF_H_LT : out + (size_t)N_BV * D;
        float* dst_cm = (l == 0) ? buf + OF_H_CM : out + (size_t)(N_BV + N_LT) * D;
        float* dst_dn = (l == 0) ? buf + OF_H_DN : out + (size_t)(N_BV + N_LT + N_CM) * D;
        const float* Wl = convW + (size_t)l * 4 * 32768;

        // src-side transforms for e0 (lt->bv) and e1 (cm->bv): z = h_src @ W_bot
        gemm128_kernel<<<(N_LT + 63) / 64, 256>>>(cur_lt, N_LT, Wl + 0 * 32768 + 16384, nullptr, nullptr, z_lt, 0);
        gemm128_kernel<<<(N_CM + 63) / 64, 256>>>(cur_cm, N_CM, Wl + 1 * 32768 + 16384, nullptr, nullptr, z_cm, 0);

        cudaMemsetAsync(buf + OF_AGG0, 0, (OF_AGG_END - OF_AGG0) * sizeof(float), 0);

        edge_agg_kernel<<<(E0_N + 7) / 8, 256>>>(src0, dst0, z_lt,   agg0, E0_N);
        edge_agg_kernel<<<(E1_N + 7) / 8, 256>>>(src1, dst1, z_cm,   agg1, E1_N);
        edge_agg_kernel<<<(E2_N + 7) / 8, 256>>>(src2, dst2, cur_dn, agg2, E2_N);
        edge_agg_kernel<<<(E3_N + 7) / 8, 256>>>(src3, dst3, cur_bv, agg3, E3_N);

        // dst-side transforms
        gemm128_kernel<<<(N_BV + 63) / 64, 256>>>(cur_bv, N_BV, wcomb + l * 16384, bcomb + l * 128, nullptr, out_bv, 0);
        gemm128_kernel<<<(N_LT + 63) / 64, 256>>>(cur_lt, N_LT, Wl + 2 * 32768,         convB + (l * 4 + 2) * 128, nullptr, out_lt, 0);
        gemm128_kernel<<<(N_LT + 63) / 64, 256>>>(agg2,   N_LT, Wl + 2 * 32768 + 16384, nullptr, cnt2, out_lt, 1);
        gemm128_kernel<<<(N_CM + 63) / 64, 256>>>(cur_cm, N_CM, Wl + 3 * 32768,         convB + (l * 4 + 3) * 128, nullptr, out_cm, 0);
        gemm128_kernel<<<(N_CM + 63) / 64, 256>>>(agg3,   N_CM, Wl + 3 * 32768 + 16384, nullptr, cnt3, out_cm, 1);

        // finish + LayerNorm
        finish_ln_kernel<<<N_BV, 128>>>(out_bv, agg0, cnt0, agg1, cnt1, bias_bv, lng + 0,   lnb + 0,   dst_bv);
        finish_ln_kernel<<<N_LT, 128>>>(out_lt, nullptr, nullptr, nullptr, nullptr, bias_lt, lng + 128, lnb + 128, dst_lt);
        finish_ln_kernel<<<N_CM, 128>>>(out_cm, nullptr, nullptr, nullptr, nullptr, bias_cm, lng + 256, lnb + 256, dst_cm);
        fill_rows_kernel<<<(int)(((size_t)N_DN * D + 255) / 256), 256>>>(dst_dn, lnb + 384, (size_t)N_DN * D);
    }
}

// round 2
// speedup vs baseline: 1.5483x; 1.5483x over previous
#include <cuda_runtime.h>
#include <cstdint>
#include <cstddef>

#define D 128
#define N_BV 100000
#define N_LT 20000
#define N_CM 2000
#define N_DN 100000
#define E0_N 600000
#define E1_N 200000
#define E2_N 500000
#define E3_N 200000

// ---------------- scratch layout (float slots, 32-aligned) ----------------
constexpr size_t AL(size_t x) { return (x + 31) & ~size_t(31); }

constexpr size_t OF_MEANBV = 0;
constexpr size_t OF_AGG2   = AL(OF_MEANBV + (size_t)N_BV * D);
constexpr size_t OF_AGG3   = AL(OF_AGG2 + (size_t)N_LT * D);
constexpr size_t OF_FTS0   = AL(OF_AGG3 + (size_t)N_CM * D);
constexpr size_t OF_FTS1   = AL(OF_FTS0 + (size_t)N_BV * 16);
constexpr size_t OF_FTS2   = AL(OF_FTS1 + (size_t)N_BV * 16);
constexpr size_t OF_FTS3   = AL(OF_FTS2 + (size_t)N_LT * 16);
constexpr size_t OF_FTS_END= AL(OF_FTS3 + (size_t)N_CM * 16);
constexpr size_t OF_HBV    = OF_FTS_END;
constexpr size_t OF_HLT    = AL(OF_HBV + (size_t)N_BV * D);
constexpr size_t OF_HCM    = AL(OF_HLT + (size_t)N_LT * D);
constexpr size_t OF_ZLT    = AL(OF_HCM + (size_t)N_CM * D);
constexpr size_t OF_ZCM    = AL(OF_ZLT + (size_t)N_LT * D);
constexpr size_t OF_BBV    = AL(OF_ZCM + (size_t)N_CM * D);
constexpr size_t OF_BLT    = AL(OF_BBV + (size_t)N_BV * D);
constexpr size_t OF_BCM    = AL(OF_BLT + (size_t)N_LT * D);
constexpr size_t OF_WCOMB  = AL(OF_BCM + (size_t)N_CM * D);
constexpr size_t OF_BCOMB  = AL(OF_WCOMB + 2 * 128 * 128);
// ---- int region (aliased) ----
constexpr size_t OF_ICNT0  = AL(OF_BCOMB + 256);
constexpr size_t OF_ICNT1  = AL(OF_ICNT0 + N_BV);
constexpr size_t OF_ICNT2  = AL(OF_ICNT1 + N_BV);
constexpr size_t OF_ICNT3  = AL(OF_ICNT2 + N_LT);
constexpr size_t OF_RP0    = AL(OF_ICNT3 + N_CM);
constexpr size_t OF_RP1    = AL(OF_RP0 + N_BV + 1);
constexpr size_t OF_RP2    = AL(OF_RP1 + N_BV + 1);
constexpr size_t OF_RP3    = AL(OF_RP2 + N_LT + 1);
constexpr size_t OF_CUR0   = AL(OF_RP3 + N_CM + 1);
constexpr size_t OF_CUR1   = AL(OF_CUR0 + N_BV);
constexpr size_t OF_CUR2   = AL(OF_CUR1 + N_BV);
constexpr size_t OF_CUR3   = AL(OF_CUR2 + N_LT);
constexpr size_t OF_SS0    = AL(OF_CUR3 + N_CM);
constexpr size_t OF_SS1    = AL(OF_SS0 + E0_N);
constexpr size_t OF_SS2    = AL(OF_SS1 + E1_N);
constexpr size_t OF_SS3    = AL(OF_SS2 + E2_N);
constexpr size_t OF_BSUM   = AL(OF_SS3 + E3_N);
constexpr size_t SCRATCH_TOTAL = OF_BSUM + 1024;

__device__ __align__(128) float g_buf[SCRATCH_TOTAL];

// ---------------- helpers ----------------
__device__ __forceinline__ void red_add_v4(float* p, float4 v) {
    asm volatile("red.global.add.v4.f32 [%0], {%1, %2, %3, %4};"
                 :: "l"(p), "f"(v.x), "f"(v.y), "f"(v.z), "f"(v.w)
                 : "memory");
}

// ---------------- count (int) + Time2Vec feature segment-sum (layer-invariant) ----------------
__global__ void cnt_ft_kernel(const int* __restrict__ dst, const float* __restrict__ ft,
                              int* __restrict__ icnt, float* __restrict__ fts, int E)
{
    int i = blockIdx.x * blockDim.x + threadIdx.x;
    if (i >= E) return;
    int d = dst[i];
    atomicAdd(icnt + d, 1);
    const float4* f = reinterpret_cast<const float4*>(ft) + (size_t)i * 4;
    float* o = fts + (size_t)d * 16;
    red_add_v4(o + 0,  f[0]);
    red_add_v4(o + 4,  f[1]);
    red_add_v4(o + 8,  f[2]);
    red_add_v4(o + 12, f[3]);
}

// ---------------- scan: exclusive prefix sum over int counts ----------------
__global__ void scan_block_kernel(const int* __restrict__ in, int n,
                                  int* __restrict__ out, int* __restrict__ bsum)
{
    __shared__ int sh[1024];
    int i = blockIdx.x * 1024 + threadIdx.x;
    int v = (i < n) ? in[i] : 0;
    sh[threadIdx.x] = v;
    __syncthreads();
    for (int off = 1; off < 1024; off <<= 1) {
        int t = (threadIdx.x >= (unsigned)off) ? sh[threadIdx.x - off] : 0;
        __syncthreads();
        sh[threadIdx.x] += t;
        __syncthreads();
    }
    if (i < n) out[i] = sh[threadIdx.x] - v;
    if (threadIdx.x == 1023) bsum[blockIdx.x] = sh[1023];
}

__global__ void scan_small_kernel(int* __restrict__ b, int n)
{
    __shared__ int sh[1024];
    int v = ((int)threadIdx.x < n) ? b[threadIdx.x] : 0;
    sh[threadIdx.x] = v;
    __syncthreads();
    for (int off = 1; off < 1024; off <<= 1) {
        int t = (threadIdx.x >= (unsigned)off) ? sh[threadIdx.x - off] : 0;
        __syncthreads();
        sh[threadIdx.x] += t;
        __syncthreads();
    }
    if ((int)threadIdx.x < n) b[threadIdx.x] = sh[threadIdx.x] - v;
}

__global__ void scan_add_kernel(int* __restrict__ out, const int* __restrict__ bsum,
                                int n, int total)
{
    int i = blockIdx.x * blockDim.x + threadIdx.x;
    if (i < n) out[i] += bsum[i >> 10];
    if (i == 0) out[n] = total;
}

// ---------------- CSR scatter: srcs sorted by dst ----------------
__global__ void scatter_kernel(const int* __restrict__ src, const int* __restrict__ dst,
                               int* __restrict__ cursor, int* __restrict__ ss, int E)
{
    int i = blockIdx.x * blockDim.x + threadIdx.x;
    if (i >= E) return;
    int d = dst[i];
    int p = atomicAdd(cursor + d, 1);
    ss[p] = src[i];
}

// ---------------- edge-bias precompute: (seg_sum(ft)/c) @ emlpW + (c>0)*emlp_b ----------------
__global__ void bias_pre_kernel(const float* __restrict__ fts, const int* __restrict__ icnt,
                                const float* __restrict__ Wml, const float* __restrict__ bml,
                                float* __restrict__ out, int acc)
{
    int row = blockIdx.x;
    int c = threadIdx.x;
    __shared__ float f[16];
    if (c < 16) f[c] = fts[(size_t)row * 16 + c];
    __syncthreads();
    int cv = icnt[row];
    float inv = (cv > 0) ? 1.0f / (float)cv : 0.0f;
    float a = 0.0f;
#pragma unroll
    for (int j = 0; j < 16; j++) a = fmaf(f[j], Wml[j * 128 + c], a);
    a *= inv;
    if (cv > 0) a += bml[c];
    size_t o = (size_t)row * 128 + c;
    if (acc) a += out[o];
    out[o] = a;
}

// ---------------- combine W_top of the two bv-targeting edge types ----------------
__global__ void wprep_kernel(const float* __restrict__ convW, const float* __restrict__ convB,
                             float* __restrict__ wcomb, float* __restrict__ bcomb)
{
    int idx = blockIdx.x * blockDim.x + threadIdx.x;
    if (idx < 2 * 128 * 128) {
        int l = idx >> 14;
        int rc = idx & 16383;
        wcomb[idx] = convW[(size_t)(l * 4 + 0) * 32768 + rc] +
                     convW[(size_t)(l * 4 + 1) * 32768 + rc];
    }
    if (idx < 256) {
        int l = idx >> 7, c = idx & 127;
        bcomb[idx] = convB[(l * 4 + 0) * 128 + c] + convB[(l * 4 + 1) * 128 + c];
    }
}

// ---------------- CSR mean aggregation (no atomics), warp per dst row ----------------
__global__ void csr_mean1_kernel(const int* __restrict__ rp, const int* __restrict__ ss,
                                 const float* __restrict__ X, float* __restrict__ out, int n)
{
    int w = (int)((blockIdx.x * blockDim.x + threadIdx.x) >> 5);
    int lane = threadIdx.x & 31;
    if (w >= n) return;
    int b = rp[w], e = rp[w + 1];
    float4 acc = make_float4(0.f, 0.f, 0.f, 0.f);
    for (int j = b; j < e; j++) {
        int s = __ldg(ss + j);
        float4 v = __ldg(reinterpret_cast<const float4*>(X + (size_t)s * 128) + lane);
        acc.x += v.x; acc.y += v.y; acc.z += v.z; acc.w += v.w;
    }
    float inv = (e > b) ? 1.0f / (float)(e - b) : 0.0f;
    acc.x *= inv; acc.y *= inv; acc.z *= inv; acc.w *= inv;
    reinterpret_cast<float4*>(out + (size_t)w * 128)[lane] = acc;
}

// Combined: mean over CSR0 of X0 plus mean over CSR1 of X1 (both target same dst table)
__global__ void csr_mean2_kernel(const int* __restrict__ rp0, const int* __restrict__ ss0,
                                 const float* __restrict__ X0,
                                 const int* __restrict__ rp1, const int* __restrict__ ss1,
                                 const float* __restrict__ X1,
                                 float* __restrict__ out, int n)
{
    int w = (int)((blockIdx.x * blockDim.x + threadIdx.x) >> 5);
    int lane = threadIdx.x & 31;
    if (w >= n) return;
    float4 r = make_float4(0.f, 0.f, 0.f, 0.f);
    {
        int b = rp0[w], e = rp0[w + 1];
        float4 acc = make_float4(0.f, 0.f, 0.f, 0.f);
        for (int j = b; j < e; j++) {
            int s = __ldg(ss0 + j);
            float4 v = __ldg(reinterpret_cast<const float4*>(X0 + (size_t)s * 128) + lane);
            acc.x += v.x; acc.y += v.y; acc.z += v.z; acc.w += v.w;
        }
        float inv = (e > b) ? 1.0f / (float)(e - b) : 0.0f;
        r.x += acc.x * inv; r.y += acc.y * inv; r.z += acc.z * inv; r.w += acc.w * inv;
    }
    {
        int b = rp1[w], e = rp1[w + 1];
        float4 acc = make_float4(0.f, 0.f, 0.f, 0.f);
        for (int j = b; j < e; j++) {
            int s = __ldg(ss1 + j);
            float4 v = __ldg(reinterpret_cast<const float4*>(X1 + (size_t)s * 128) + lane);
            acc.x += v.x; acc.y += v.y; acc.z += v.z; acc.w += v.w;
        }
        float inv = (e > b) ? 1.0f / (float)(e - b) : 0.0f;
        r.x += acc.x * inv; r.y += acc.y * inv; r.z += acc.z * inv; r.w += acc.w * inv;
    }
    reinterpret_cast<float4*>(out + (size_t)w * 128)[lane] = r;
}

// ---------------- layer-2 e2 shortcut: mean of identical ln_b rows -> ln_b where deg>0 ----------------
__global__ void fill_cond_kernel(const int* __restrict__ rp, const float* __restrict__ vec,
                                 float* __restrict__ out, int n)
{
    int row = blockIdx.x, c = threadIdx.x;
    float v = (rp[row + 1] > rp[row]) ? vec[c] : 0.0f;
    out[(size_t)row * 128 + c] = v;
}

// ---------------- dn final output: LN(0) = ln_b broadcast ----------------
__global__ void fill_rows_kernel(float* __restrict__ dest, const float* __restrict__ b, size_t total)
{
    size_t i = (size_t)blockIdx.x * blockDim.x + threadIdx.x;
    if (i < total) dest[i] = b[i & 127];
}

// ---------------- fused GEMM (+optional second A / bias / adds / LayerNorm) ----------------
// C[M,128] = [A1 (; A2)] @ W[K,128]  (+ bvec) (+ add1) (+ add2), optional LN(g,b)
template<int BM>
__global__ __launch_bounds__(256, 2) void gemm_fused(
    const float* __restrict__ A1, const float* __restrict__ A2, int M,
    const float* __restrict__ W, int Kchunks,
    const float* __restrict__ bvec,
    const float* __restrict__ add1, const float* __restrict__ add2,
    const float* __restrict__ lng, const float* __restrict__ lnb,
    float* __restrict__ C)
{
    constexpr int RI = BM / 16;          // rows per thread
    constexpr int NF4A = BM / 32;        // A-tile float4 loads per thread
    __shared__ float As[32][BM + 4];     // transposed: [k][row]
    __shared__ float Ws[32][128];
    int tid = threadIdx.x;
    int row0 = blockIdx.x * BM;
    int tr = tid >> 4, tc = tid & 15;

    float acc[RI][8];
#pragma unroll
    for (int i = 0; i < RI; i++)
#pragma unroll
        for (int j = 0; j < 8; j++) acc[i][j] = 0.0f;

    for (int kc = 0; kc < Kchunks; kc++) {
        const float* Asrc = (kc < 4) ? A1 : A2;
        int kk = (kc & 3) * 32;
        // load A tile (BM x 32), transpose into As
#pragma unroll
        for (int t = 0; t < NF4A; t++) {
            int f4 = tid + t * 256;
            int r = f4 >> 3, c4 = f4 & 7;
            int gr = row0 + r;
            float4 v = make_float4(0.f, 0.f, 0.f, 0.f);
            if (gr < M) v = *reinterpret_cast<const float4*>(Asrc + (size_t)gr * 128 + kk + c4 * 4);
            As[c4 * 4 + 0][r] = v.x;
            As[c4 * 4 + 1][r] = v.y;
            As[c4 * 4 + 2][r] = v.z;
            As[c4 * 4 + 3][r] = v.w;
        }
        // load W tile (32 x 128)
#pragma unroll
        for (int t = 0; t < 4; t++) {
            int f4 = tid + t * 256;
            int r = f4 >> 5, c4 = f4 & 31;
            *reinterpret_cast<float4*>(&Ws[r][c4 * 4]) =
                *reinterpret_cast<const float4*>(W + (size_t)(kc * 32 + r) * 128 + c4 * 4);
        }
        __syncthreads();
#pragma unroll 8
        for (int k = 0; k < 32; k++) {
            float av[RI];
            if constexpr (RI == 8) {
                float4 a0 = *reinterpret_cast<const float4*>(&As[k][tr * 8]);
                float4 a1 = *reinterpret_cast<const float4*>(&As[k][tr * 8 + 4]);
                av[0] = a0.x; av[1] = a0.y; av[2] = a0.z; av[3] = a0.w;
                av[4] = a1.x; av[5] = a1.y; av[6] = a1.z; av[7] = a1.w;
            } else {
                float2 a0 = *reinterpret_cast<const float2*>(&As[k][tr * 2]);
                av[0] = a0.x; av[1] = a0.y;
            }
            float4 b0 = *reinterpret_cast<const float4*>(&Ws[k][tc * 8]);
            float4 b1 = *reinterpret_cast<const float4*>(&Ws[k][tc * 8 + 4]);
            float bb[8] = {b0.x, b0.y, b0.z, b0.w, b1.x, b1.y, b1.z, b1.w};
#pragma unroll
            for (int i = 0; i < RI; i++)
#pragma unroll
                for (int j = 0; j < 8; j++) acc[i][j] = fmaf(av[i], bb[j], acc[i][j]);
        }
        __syncthreads();
    }

    // epilogue
#pragma unroll
    for (int i = 0; i < RI; i++) {
        int gr = row0 + tr * RI + i;
        bool ok = gr < M;
        float o[8];
#pragma unroll
        for (int j = 0; j < 8; j++) o[j] = acc[i][j];
        if (bvec) {
#pragma unroll
            for (int j = 0; j < 8; j++) o[j] += bvec[tc * 8 + j];
        }
        if (add1 && ok) {
            float4 p0 = *reinterpret_cast<const float4*>(add1 + (size_t)gr * 128 + tc * 8);
            float4 p1 = *reinterpret_cast<const float4*>(add1 + (size_t)gr * 128 + tc * 8 + 4);
            o[0] += p0.x; o[1] += p0.y; o[2] += p0.z; o[3] += p0.w;
            o[4] += p1.x; o[5] += p1.y; o[6] += p1.z; o[7] += p1.w;
        }
        if (add2 && ok) {
            float4 p0 = *reinterpret_cast<const float4*>(add2 + (size_t)gr * 128 + tc * 8);
            float4 p1 = *reinterpret_cast<const float4*>(add2 + (size_t)gr * 128 + tc * 8 + 4);
            o[0] += p0.x; o[1] += p0.y; o[2] += p0.z; o[3] += p0.w;
            o[4] += p1.x; o[5] += p1.y; o[6] += p1.z; o[7] += p1.w;
        }
        if (lng) {
            float s = 0.f, s2 = 0.f;
#pragma unroll
            for (int j = 0; j < 8; j++) { s += o[j]; s2 += o[j] * o[j]; }
#pragma unroll
            for (int off = 1; off < 16; off <<= 1) {
                s  += __shfl_xor_sync(0xffffffffu, s,  off, 16);
                s2 += __shfl_xor_sync(0xffffffffu, s2, off, 16);
            }
            float m = s * (1.0f / 128.0f);
            float var = s2 * (1.0f / 128.0f) - m * m;
            float rs = rsqrtf(var + 1e-5f);
#pragma unroll
            for (int j = 0; j < 8; j++)
                o[j] = (o[j] - m) * rs * lng[tc * 8 + j] + lnb[tc * 8 + j];
        }
        if (ok) {
            float* cp = C + (size_t)gr * 128 + tc * 8;
            *reinterpret_cast<float4*>(cp)     = make_float4(o[0], o[1], o[2], o[3]);
            *reinterpret_cast<float4*>(cp + 4) = make_float4(o[4], o[5], o[6], o[7]);
        }
    }
}

// ---------------- host-side scan helper ----------------
static void run_scan(int* rp /*counts already copied in [0..n)*/, const int* icnt,
                     int* bsum, int n, int total)
{
    int nb = (n + 1023) / 1024;
    scan_block_kernel<<<nb, 1024>>>(icnt, n, rp, bsum);
    scan_small_kernel<<<1, 1024>>>(bsum, nb);
    scan_add_kernel<<<(n + 255) / 256, 256>>>(rp, bsum, n, total);
}

// ---------------- launch ----------------
extern "C" void kernel_launch(void* const* d_in, const int* in_sizes, int n_in,
                              void* d_out, int out_size)
{
    (void)in_sizes; (void)n_in; (void)out_size;
    const float* h0_bv = (const float*)d_in[0];
    const float* h0_lt = (const float*)d_in[1];
    const float* h0_cm = (const float*)d_in[2];
    const float* h0_dn = (const float*)d_in[3];
    const float* ft0 = (const float*)d_in[4];
    const float* ft1 = (const float*)d_in[5];
    const float* ft2 = (const float*)d_in[6];
    const float* ft3 = (const float*)d_in[7];
    const float* convW = (const float*)d_in[8];
    const float* convB = (const float*)d_in[9];
    const float* emlpW = (const float*)d_in[10];
    const float* emlpB = (const float*)d_in[11];
    const float* lng = (const float*)d_in[12];
    const float* lnb = (const float*)d_in[13];
    const int* src0 = (const int*)d_in[14];
    const int* dst0 = (const int*)d_in[15];
    const int* src1 = (const int*)d_in[16];
    const int* dst1 = (const int*)d_in[17];
    const int* src2 = (const int*)d_in[18];
    const int* dst2 = (const int*)d_in[19];
    const int* src3 = (const int*)d_in[20];
    const int* dst3 = (const int*)d_in[21];
    float* out = (float*)d_out;

    float* buf = nullptr;
    cudaGetSymbolAddress((void**)&buf, g_buf);

    float* mean_bv = buf + OF_MEANBV;
    float* agg2 = buf + OF_AGG2;
    float* agg3 = buf + OF_AGG3;
    float* fts0 = buf + OF_FTS0;
    float* fts1 = buf + OF_FTS1;
    float* fts2 = buf + OF_FTS2;
    float* fts3 = buf + OF_FTS3;
    float* z_lt = buf + OF_ZLT;
    float* z_cm = buf + OF_ZCM;
    float* bias_bv = buf + OF_BBV;
    float* bias_lt = buf + OF_BLT;
    float* bias_cm = buf + OF_BCM;
    float* wcomb = buf + OF_WCOMB;
    float* bcomb = buf + OF_BCOMB;

    int* icnt0 = (int*)(buf + OF_ICNT0);
    int* icnt1 = (int*)(buf + OF_ICNT1);
    int* icnt2 = (int*)(buf + OF_ICNT2);
    int* icnt3 = (int*)(buf + OF_ICNT3);
    int* rp0 = (int*)(buf + OF_RP0);
    int* rp1 = (int*)(buf + OF_RP1);
    int* rp2 = (int*)(buf + OF_RP2);
    int* rp3 = (int*)(buf + OF_RP3);
    int* cur0 = (int*)(buf + OF_CUR0);
    int* cur1 = (int*)(buf + OF_CUR1);
    int* cur2 = (int*)(buf + OF_CUR2);
    int* cur3 = (int*)(buf + OF_CUR3);
    int* ss0 = (int*)(buf + OF_SS0);
    int* ss1 = (int*)(buf + OF_SS1);
    int* ss2 = (int*)(buf + OF_SS2);
    int* ss3 = (int*)(buf + OF_SS3);
    int* bsum = (int*)(buf + OF_BSUM);

    // ---- layer-invariant precompute ----
    cudaMemsetAsync(buf + OF_AGG3 /* start of fts zero region is FTS0; also zero icnt */,
                    0, 0, 0); // no-op placeholder (kept for clarity)
    cudaMemsetAsync(buf + OF_FTS0, 0, (OF_FTS_END - OF_FTS0) * sizeof(float), 0);
    cudaMemsetAsync(buf + OF_ICNT0, 0, (OF_RP0 - OF_ICNT0) * sizeof(float), 0);

    cnt_ft_kernel<<<(E0_N + 255) / 256, 256>>>(dst0, ft0, icnt0, fts0, E0_N);
    cnt_ft_kernel<<<(E1_N + 255) / 256, 256>>>(dst1, ft1, icnt1, fts1, E1_N);
    cnt_ft_kernel<<<(E2_N + 255) / 256, 256>>>(dst2, ft2, icnt2, fts2, E2_N);
    cnt_ft_kernel<<<(E3_N + 255) / 256, 256>>>(dst3, ft3, icnt3, fts3, E3_N);

    run_scan(rp0, icnt0, bsum, N_BV, E0_N);
    run_scan(rp1, icnt1, bsum, N_BV, E1_N);
    run_scan(rp2, icnt2, bsum, N_LT, E2_N);
    run_scan(rp3, icnt3, bsum, N_CM, E3_N);

    cudaMemcpyAsync(cur0, rp0, N_BV * sizeof(int), cudaMemcpyDeviceToDevice, 0);
    cudaMemcpyAsync(cur1, rp1, N_BV * sizeof(int), cudaMemcpyDeviceToDevice, 0);
    cudaMemcpyAsync(cur2, rp2, N_LT * sizeof(int), cudaMemcpyDeviceToDevice, 0);
    cudaMemcpyAsync(cur3, rp3, N_CM * sizeof(int), cudaMemcpyDeviceToDevice, 0);

    scatter_kernel<<<(E0_N + 255) / 256, 256>>>(src0, dst0, cur0, ss0, E0_N);
    scatter_kernel<<<(E1_N + 255) / 256, 256>>>(src1, dst1, cur1, ss1, E1_N);
    scatter_kernel<<<(E2_N + 255) / 256, 256>>>(src2, dst2, cur2, ss2, E2_N);
    scatter_kernel<<<(E3_N + 255) / 256, 256>>>(src3, dst3, cur3, ss3, E3_N);

    bias_pre_kernel<<<N_BV, 128>>>(fts0, icnt0, emlpW + 0 * 2048, emlpB + 0,   bias_bv, 0);
    bias_pre_kernel<<<N_BV, 128>>>(fts1, icnt1, emlpW + 1 * 2048, emlpB + 128, bias_bv, 1);
    bias_pre_kernel<<<N_LT, 128>>>(fts2, icnt2, emlpW + 2 * 2048, emlpB + 256, bias_lt, 0);
    bias_pre_kernel<<<N_CM, 128>>>(fts3, icnt3, emlpW + 3 * 2048, emlpB + 384, bias_cm, 0);

    wprep_kernel<<<(2 * 128 * 128 + 255) / 256, 256>>>(convW, convB, wcomb, bcomb);

    for (int l = 0; l < 2; l++) {
        const float* cur_bv = (l == 0) ? h0_bv : buf + OF_HBV;
        const float* cur_lt = (l == 0) ? h0_lt : buf + OF_HLT;
        const float* cur_cm = (l == 0) ? h0_cm : buf + OF_HCM;
        float* dst_bv = (l == 0) ? buf + OF_HBV : out;
        float* dst_lt = (l == 0) ? buf + OF_HLT : out + (size_t)N_BV * D;
        float* dst_cm = (l == 0) ? buf + OF_HCM : out + (size_t)(N_BV + N_LT) * D;
        const float* Wl = convW + (size_t)l * 4 * 32768;

        // src-side transforms: z = h_src @ W_bot for e0 (lt->bv), e1 (cm->bv)
        gemm_fused<128><<<(N_LT + 127) / 128, 256>>>(
            cur_lt, nullptr, N_LT, Wl + 0 * 32768 + 16384, 4,
            nullptr, nullptr, nullptr, nullptr, nullptr, z_lt);
        gemm_fused<32><<<(N_CM + 31) / 32, 256>>>(
            cur_cm, nullptr, N_CM, Wl + 1 * 32768 + 16384, 4,
            nullptr, nullptr, nullptr, nullptr, nullptr, z_cm);

        // CSR mean aggregations (no atomics)
        csr_mean2_kernel<<<(N_BV * 32 + 255) / 256, 256>>>(
            rp0, ss0, z_lt, rp1, ss1, z_cm, mean_bv, N_BV);
        if (l == 0) {
            csr_mean1_kernel<<<(N_LT * 32 + 255) / 256, 256>>>(rp2, ss2, h0_dn, agg2, N_LT);
        } else {
            // layer-2 h_dn rows are all ln_b[3] -> mean is ln_b[3] where deg>0
            fill_cond_kernel<<<N_LT, 128>>>(rp2, lnb + 384, agg2, N_LT);
        }
        csr_mean1_kernel<<<(N_CM * 32 + 255) / 256, 256>>>(rp3, ss3, cur_bv, agg3, N_CM);

        // fused conv + LayerNorm per dst type
        gemm_fused<128><<<(N_BV + 127) / 128, 256>>>(
            cur_bv, nullptr, N_BV, wcomb + l * 16384, 4,
            bcomb + l * 128, mean_bv, bias_bv, lng + 0, lnb + 0, dst_bv);
        gemm_fused<128><<<(N_LT + 127) / 128, 256>>>(
            cur_lt, agg2, N_LT, Wl + 2 * 32768, 8,
            convB + (l * 4 + 2) * 128, bias_lt, nullptr, lng + 128, lnb + 128, dst_lt);
        gemm_fused<32><<<(N_CM + 31) / 32, 256>>>(
            cur_cm, agg3, N_CM, Wl + 3 * 32768, 8,
            convB + (l * 4 + 3) * 128, bias_cm, nullptr, lng + 256, lnb + 256, dst_cm);
    }

    // dn output: LN(zeros) = ln_b[3] broadcast (both layers produce the same)
    fill_rows_kernel<<<(int)(((size_t)N_DN * D + 255) / 256), 256>>>(
        out + (size_t)(N_BV + N_LT + N_CM) * D, lnb + 384, (size_t)N_DN * D);
}

// round 3
// speedup vs baseline: 1.7561x; 1.1342x over previous
#include <cuda_runtime.h>
#include <cuda_bf16.h>
#include <cstdint>
#include <cstddef>

#define D 128
#define N_BV 100000
#define N_LT 20000
#define N_CM 2000
#define N_DN 100000
#define E0_N 600000
#define E1_N 200000
#define E2_N 500000
#define E3_N 200000

// ---------------- scratch layout (float slots, 32-aligned) ----------------
constexpr size_t AL(size_t x) { return (x + 31) & ~size_t(31); }

// packed split weights: 2 layers x 28 chunks x 8192 ushort (hi 128x32 + lo 128x32, [n][k])
constexpr size_t WS_USHORTS = 2 * 28 * 8192;
constexpr size_t WS_FLOATS  = WS_USHORTS / 2;

constexpr size_t OF_MEANBV = 0;
constexpr size_t OF_AGG2   = AL(OF_MEANBV + (size_t)N_BV * D);
constexpr size_t OF_AGG3   = AL(OF_AGG2 + (size_t)N_LT * D);
constexpr size_t OF_FTS0   = AL(OF_AGG3 + (size_t)N_CM * D);
constexpr size_t OF_FTS1   = AL(OF_FTS0 + (size_t)N_BV * 16);
constexpr size_t OF_FTS2   = AL(OF_FTS1 + (size_t)N_BV * 16);
constexpr size_t OF_FTS3   = AL(OF_FTS2 + (size_t)N_LT * 16);
constexpr size_t OF_FTS_END= AL(OF_FTS3 + (size_t)N_CM * 16);
constexpr size_t OF_HBV    = OF_FTS_END;
constexpr size_t OF_HLT    = AL(OF_HBV + (size_t)N_BV * D);
constexpr size_t OF_HCM    = AL(OF_HLT + (size_t)N_LT * D);
constexpr size_t OF_ZLT    = AL(OF_HCM + (size_t)N_CM * D);
constexpr size_t OF_ZCM    = AL(OF_ZLT + (size_t)N_LT * D);
constexpr size_t OF_BBV    = AL(OF_ZCM + (size_t)N_CM * D);
constexpr size_t OF_BLT    = AL(OF_BBV + (size_t)N_BV * D);
constexpr size_t OF_BCM    = AL(OF_BLT + (size_t)N_LT * D);
constexpr size_t OF_WS     = AL(OF_BCM + (size_t)N_CM * D);
constexpr size_t OF_BCOMB  = AL(OF_WS + WS_FLOATS);
// ---- int region (aliased) ----
constexpr size_t OF_ICNT0  = AL(OF_BCOMB + 256);
constexpr size_t OF_ICNT1  = AL(OF_ICNT0 + N_BV);
constexpr size_t OF_ICNT2  = AL(OF_ICNT1 + N_BV);
constexpr size_t OF_ICNT3  = AL(OF_ICNT2 + N_LT);
constexpr size_t OF_RP0    = AL(OF_ICNT3 + N_CM);
constexpr size_t OF_RP1    = AL(OF_RP0 + N_BV + 1);
constexpr size_t OF_RP2    = AL(OF_RP1 + N_BV + 1);
constexpr size_t OF_RP3    = AL(OF_RP2 + N_LT + 1);
constexpr size_t OF_CUR0   = AL(OF_RP3 + N_CM + 1);
constexpr size_t OF_CUR1   = AL(OF_CUR0 + N_BV);
constexpr size_t OF_CUR2   = AL(OF_CUR1 + N_BV);
constexpr size_t OF_CUR3   = AL(OF_CUR2 + N_LT);
constexpr size_t OF_SS0    = AL(OF_CUR3 + N_CM);
constexpr size_t OF_SS1    = AL(OF_SS0 + E0_N);
constexpr size_t OF_SS2    = AL(OF_SS1 + E1_N);
constexpr size_t OF_SS3    = AL(OF_SS2 + E2_N);
constexpr size_t OF_BSUM   = AL(OF_SS3 + E3_N);
constexpr size_t SCRATCH_TOTAL = OF_BSUM + 1024;

__device__ __align__(128) float g_buf[SCRATCH_TOTAL];

// ---------------- helpers ----------------
__device__ __forceinline__ void red_add_v4(float* p, float4 v) {
    asm volatile("red.global.add.v4.f32 [%0], {%1, %2, %3, %4};"
                 :: "l"(p), "f"(v.x), "f"(v.y), "f"(v.z), "f"(v.w)
                 : "memory");
}

__device__ __forceinline__ unsigned short f2bf(float x) {
    __nv_bfloat16 h = __float2bfloat16(x);
    return *reinterpret_cast<unsigned short*>(&h);
}
__device__ __forceinline__ float bf2f(unsigned short u) {
    __nv_bfloat16 h;
    *reinterpret_cast<unsigned short*>(&h) = u;
    return __bfloat162float(h);
}

#define MMA_BF16(d, a0, a1, a2, a3, b0, b1) \
    asm volatile("mma.sync.aligned.m16n8k16.row.col.f32.bf16.bf16.f32 " \
                 "{%0,%1,%2,%3},{%4,%5,%6,%7},{%8,%9},{%0,%1,%2,%3};" \
                 : "+f"(d[0]), "+f"(d[1]), "+f"(d[2]), "+f"(d[3]) \
                 : "r"(a0), "r"(a1), "r"(a2), "r"(a3), "r"(b0), "r"(b1))

// ---------------- count (int) + Time2Vec feature segment-sum (layer-invariant) ----------------
__global__ void cnt_ft_kernel(const int* __restrict__ dst, const float* __restrict__ ft,
                              int* __restrict__ icnt, float* __restrict__ fts, int E)
{
    int i = blockIdx.x * blockDim.x + threadIdx.x;
    if (i >= E) return;
    int d = dst[i];
    atomicAdd(icnt + d, 1);
    const float4* f = reinterpret_cast<const float4*>(ft) + (size_t)i * 4;
    float* o = fts + (size_t)d * 16;
    red_add_v4(o + 0,  f[0]);
    red_add_v4(o + 4,  f[1]);
    red_add_v4(o + 8,  f[2]);
    red_add_v4(o + 12, f[3]);
}

// ---------------- scan ----------------
__global__ void scan_block_kernel(const int* __restrict__ in, int n,
                                  int* __restrict__ out, int* __restrict__ bsum)
{
    __shared__ int sh[1024];
    int i = blockIdx.x * 1024 + threadIdx.x;
    int v = (i < n) ? in[i] : 0;
    sh[threadIdx.x] = v;
    __syncthreads();
    for (int off = 1; off < 1024; off <<= 1) {
        int t = (threadIdx.x >= (unsigned)off) ? sh[threadIdx.x - off] : 0;
        __syncthreads();
        sh[threadIdx.x] += t;
        __syncthreads();
    }
    if (i < n) out[i] = sh[threadIdx.x] - v;
    if (threadIdx.x == 1023) bsum[blockIdx.x] = sh[1023];
}

__global__ void scan_small_kernel(int* __restrict__ b, int n)
{
    __shared__ int sh[1024];
    int v = ((int)threadIdx.x < n) ? b[threadIdx.x] : 0;
    sh[threadIdx.x] = v;
    __syncthreads();
    for (int off = 1; off < 1024; off <<= 1) {
        int t = (threadIdx.x >= (unsigned)off) ? sh[threadIdx.x - off] : 0;
        __syncthreads();
        sh[threadIdx.x] += t;
        __syncthreads();
    }
    if ((int)threadIdx.x < n) b[threadIdx.x] = sh[threadIdx.x] - v;
}

__global__ void scan_add_kernel(int* __restrict__ out, const int* __restrict__ bsum,
                                int n, int total)
{
    int i = blockIdx.x * blockDim.x + threadIdx.x;
    if (i < n) out[i] += bsum[i >> 10];
    if (i == 0) out[n] = total;
}

// ---------------- CSR scatter ----------------
__global__ void scatter_kernel(const int* __restrict__ src, const int* __restrict__ dst,
                               int* __restrict__ cursor, int* __restrict__ ss, int E)
{
    int i = blockIdx.x * blockDim.x + threadIdx.x;
    if (i >= E) return;
    int d = dst[i];
    int p = atomicAdd(cursor + d, 1);
    ss[p] = src[i];
}

// ---------------- edge-bias precompute ----------------
__global__ void bias_pre_kernel(const float* __restrict__ fts, const int* __restrict__ icnt,
                                const float* __restrict__ Wml, const float* __restrict__ bml,
                                float* __restrict__ out, int acc)
{
    int row = blockIdx.x;
    int c = threadIdx.x;
    __shared__ float f[16];
    if (c < 16) f[c] = fts[(size_t)row * 16 + c];
    __syncthreads();
    int cv = icnt[row];
    float inv = (cv > 0) ? 1.0f / (float)cv : 0.0f;
    float a = 0.0f;
#pragma unroll
    for (int j = 0; j < 16; j++) a = fmaf(f[j], Wml[j * 128 + c], a);
    a *= inv;
    if (cv > 0) a += bml[c];
    size_t o = (size_t)row * 128 + c;
    if (acc) a += out[o];
    out[o] = a;
}

// ---------------- combined bias for bv (e0+e1) ----------------
__global__ void bprep_kernel(const float* __restrict__ convB, float* __restrict__ bcomb)
{
    int idx = threadIdx.x;
    if (idx < 256) {
        int l = idx >> 7, c = idx & 127;
        bcomb[idx] = convB[(l * 4 + 0) * 128 + c] + convB[(l * 4 + 1) * 128 + c];
    }
}

// ---------------- weight split: fp32 [32k x 128n] chunk -> bf16 hi/lo transposed [n][k] ----------------
__global__ void wsplit_kernel(const float* __restrict__ W, const float* __restrict__ W2,
                              unsigned short* __restrict__ outb)
{
    int k0 = blockIdx.x * 32;
    unsigned short* o = outb + (size_t)blockIdx.x * 8192;
#pragma unroll
    for (int t = 0; t < 16; t++) {
        int e = threadIdx.x + t * 256;      // 0..4095
        int k = e >> 7;                     // 0..31
        int n = e & 127;
        float w = W[(size_t)(k0 + k) * 128 + n];
        if (W2) w += W2[(size_t)(k0 + k) * 128 + n];
        unsigned short hi = f2bf(w);
        unsigned short lo = f2bf(w - bf2f(hi));
        o[n * 32 + k] = hi;
        o[4096 + n * 32 + k] = lo;
    }
}

// ---------------- CSR mean aggregation ----------------
__global__ void csr_mean1_kernel(const int* __restrict__ rp, const int* __restrict__ ss,
                                 const float* __restrict__ X, float* __restrict__ out, int n)
{
    int w = (int)((blockIdx.x * blockDim.x + threadIdx.x) >> 5);
    int lane = threadIdx.x & 31;
    if (w >= n) return;
    int b = rp[w], e = rp[w + 1];
    float4 acc = make_float4(0.f, 0.f, 0.f, 0.f);
    for (int j = b; j < e; j++) {
        int s = __ldg(ss + j);
        float4 v = __ldg(reinterpret_cast<const float4*>(X + (size_t)s * 128) + lane);
        acc.x += v.x; acc.y += v.y; acc.z += v.z; acc.w += v.w;
    }
    float inv = (e > b) ? 1.0f / (float)(e - b) : 0.0f;
    acc.x *= inv; acc.y *= inv; acc.z *= inv; acc.w *= inv;
    reinterpret_cast<float4*>(out + (size_t)w * 128)[lane] = acc;
}

__global__ void csr_mean2_kernel(const int* __restrict__ rp0, const int* __restrict__ ss0,
                                 const float* __restrict__ X0,
                                 const int* __restrict__ rp1, const int* __restrict__ ss1,
                                 const float* __restrict__ X1,
                                 float* __restrict__ out, int n)
{
    int w = (int)((blockIdx.x * blockDim.x + threadIdx.x) >> 5);
    int lane = threadIdx.x & 31;
    if (w >= n) return;
    float4 r = make_float4(0.f, 0.f, 0.f, 0.f);
    {
        int b = rp0[w], e = rp0[w + 1];
        float4 acc = make_float4(0.f, 0.f, 0.f, 0.f);
        for (int j = b; j < e; j++) {
            int s = __ldg(ss0 + j);
            float4 v = __ldg(reinterpret_cast<const float4*>(X0 + (size_t)s * 128) + lane);
            acc.x += v.x; acc.y += v.y; acc.z += v.z; acc.w += v.w;
        }
        float inv = (e > b) ? 1.0f / (float)(e - b) : 0.0f;
        r.x += acc.x * inv; r.y += acc.y * inv; r.z += acc.z * inv; r.w += acc.w * inv;
    }
    {
        int b = rp1[w], e = rp1[w + 1];
        float4 acc = make_float4(0.f, 0.f, 0.f, 0.f);
        for (int j = b; j < e; j++) {
            int s = __ldg(ss1 + j);
            float4 v = __ldg(reinterpret_cast<const float4*>(X1 + (size_t)s * 128) + lane);
            acc.x += v.x; acc.y += v.y; acc.z += v.z; acc.w += v.w;
        }
        float inv = (e > b) ? 1.0f / (float)(e - b) : 0.0f;
        r.x += acc.x * inv; r.y += acc.y * inv; r.z += acc.z * inv; r.w += acc.w * inv;
    }
    reinterpret_cast<float4*>(out + (size_t)w * 128)[lane] = r;
}

// ---------------- layer-2 e2 shortcut ----------------
__global__ void fill_cond_kernel(const int* __restrict__ rp, const float* __restrict__ vec,
                                 float* __restrict__ out, int n)
{
    int row = blockIdx.x, c = threadIdx.x;
    float v = (rp[row + 1] > rp[row]) ? vec[c] : 0.0f;
    out[(size_t)row * 128 + c] = v;
}

// ---------------- dn output fill ----------------
__global__ void fill_rows_kernel(float* __restrict__ dest, const float* __restrict__ b, size_t total)
{
    size_t i = (size_t)blockIdx.x * blockDim.x + threadIdx.x;
    if (i < total) dest[i] = b[i & 127];
}

// ---------------- tensor-core split-bf16 GEMM + fused epilogue ----------------
// C[M,128] = [A1 (; A2)] @ Wsplit  (+ bvec)(+ add1)(+ add2), optional LayerNorm(g,b)
// Wsplit: per 32-k chunk: 4096 ushort hi [n=128][k=32] then 4096 ushort lo.
__global__ __launch_bounds__(256, 2) void gemm_tc(
    const float* __restrict__ A1, const float* __restrict__ A2, int M,
    const unsigned short* __restrict__ wsp, int Kchunks,
    const float* __restrict__ bvec,
    const float* __restrict__ add1, const float* __restrict__ add2,
    const float* __restrict__ lng, const float* __restrict__ lnb,
    float* __restrict__ C)
{
    __shared__ unsigned short Ah[128][40], Alo[128][40];
    __shared__ unsigned short Bh[128][40], Bl[128][40];
    int tid = threadIdx.x;
    int wid = tid >> 5, lane = tid & 31;
    int row0 = blockIdx.x * 128;

    float acc[16][4];
#pragma unroll
    for (int i = 0; i < 16; i++)
#pragma unroll
        for (int j = 0; j < 4; j++) acc[i][j] = 0.0f;

    for (int kc = 0; kc < Kchunks; kc++) {
        const float* Asrc = (kc < 4) ? A1 : A2;
        int kk = (kc & 3) * 32;
        // ---- load + split A tile (128 x 32) ----
#pragma unroll
        for (int t = 0; t < 4; t++) {
            int i = tid + t * 256;          // 0..1023
            int r = i >> 3;
            int kq = i & 7;
            int gr = row0 + r;
            float4 v = make_float4(0.f, 0.f, 0.f, 0.f);
            if (gr < M) v = *reinterpret_cast<const float4*>(Asrc + (size_t)gr * 128 + kk + kq * 4);
            unsigned short h0 = f2bf(v.x), h1 = f2bf(v.y), h2 = f2bf(v.z), h3 = f2bf(v.w);
            unsigned short l0 = f2bf(v.x - bf2f(h0)), l1 = f2bf(v.y - bf2f(h1));
            unsigned short l2 = f2bf(v.z - bf2f(h2)), l3 = f2bf(v.w - bf2f(h3));
            *reinterpret_cast<uint2*>(&Ah[r][kq * 4]) =
                make_uint2((uint32_t)h0 | ((uint32_t)h1 << 16), (uint32_t)h2 | ((uint32_t)h3 << 16));
            *reinterpret_cast<uint2*>(&Alo[r][kq * 4]) =
                make_uint2((uint32_t)l0 | ((uint32_t)l1 << 16), (uint32_t)l2 | ((uint32_t)l3 << 16));
        }
        // ---- copy pre-split W chunk ----
        const uint4* wp = reinterpret_cast<const uint4*>(wsp + (size_t)kc * 8192);
#pragma unroll
        for (int t = 0; t < 2; t++) {
            int i = tid + t * 256;          // 0..511
            int n = i >> 2;
            int kq = i & 3;
            *reinterpret_cast<uint4*>(&Bh[n][kq * 8]) = wp[i];
            *reinterpret_cast<uint4*>(&Bl[n][kq * 8]) = wp[512 + i];
        }
        __syncthreads();
        // ---- MMA ----
#pragma unroll
        for (int ks = 0; ks < 2; ks++) {
            int ac = ks * 16 + (lane & 3) * 2;
            int ar = wid * 16 + (lane >> 2);
            uint32_t ah0 = *reinterpret_cast<const uint32_t*>(&Ah[ar][ac]);
            uint32_t ah1 = *reinterpret_cast<const uint32_t*>(&Ah[ar + 8][ac]);
            uint32_t ah2 = *reinterpret_cast<const uint32_t*>(&Ah[ar][ac + 8]);
            uint32_t ah3 = *reinterpret_cast<const uint32_t*>(&Ah[ar + 8][ac + 8]);
            uint32_t al0 = *reinterpret_cast<const uint32_t*>(&Alo[ar][ac]);
            uint32_t al1 = *reinterpret_cast<const uint32_t*>(&Alo[ar + 8][ac]);
            uint32_t al2 = *reinterpret_cast<const uint32_t*>(&Alo[ar][ac + 8]);
            uint32_t al3 = *reinterpret_cast<const uint32_t*>(&Alo[ar + 8][ac + 8]);
#pragma unroll
            for (int nt = 0; nt < 16; nt++) {
                int bn = nt * 8 + (lane >> 2);
                uint32_t bh0 = *reinterpret_cast<const uint32_t*>(&Bh[bn][ac]);
                uint32_t bh1 = *reinterpret_cast<const uint32_t*>(&Bh[bn][ac + 8]);
                uint32_t bl0 = *reinterpret_cast<const uint32_t*>(&Bl[bn][ac]);
                uint32_t bl1 = *reinterpret_cast<const uint32_t*>(&Bl[bn][ac + 8]);
                MMA_BF16(acc[nt], ah0, ah1, ah2, ah3, bh0, bh1);
                MMA_BF16(acc[nt], ah0, ah1, ah2, ah3, bl0, bl1);
                MMA_BF16(acc[nt], al0, al1, al2, al3, bh0, bh1);
            }
        }
        __syncthreads();
    }

    // ---- epilogue ----
    int r1 = row0 + wid * 16 + (lane >> 2);
    int r2 = r1 + 8;
    int cb = (lane & 3) * 2;
    bool ok1 = r1 < M, ok2 = r2 < M;

    float s1 = 0.f, q1 = 0.f, s2 = 0.f, q2 = 0.f;
#pragma unroll
    for (int nt = 0; nt < 16; nt++) {
        int col = nt * 8 + cb;
        if (bvec) {
            float bx = bvec[col], by = bvec[col + 1];
            acc[nt][0] += bx; acc[nt][1] += by;
            acc[nt][2] += bx; acc[nt][3] += by;
        }
        if (add1) {
            if (ok1) {
                float2 p = *reinterpret_cast<const float2*>(add1 + (size_t)r1 * 128 + col);
                acc[nt][0] += p.x; acc[nt][1] += p.y;
            }
            if (ok2) {
                float2 p = *reinterpret_cast<const float2*>(add1 + (size_t)r2 * 128 + col);
                acc[nt][2] += p.x; acc[nt][3] += p.y;
            }
        }
        if (add2) {
            if (ok1) {
                float2 p = *reinterpret_cast<const float2*>(add2 + (size_t)r1 * 128 + col);
                acc[nt][0] += p.x; acc[nt][1] += p.y;
            }
            if (ok2) {
                float2 p = *reinterpret_cast<const float2*>(add2 + (size_t)r2 * 128 + col);
                acc[nt][2] += p.x; acc[nt][3] += p.y;
            }
        }
        s1 += acc[nt][0] + acc[nt][1];
        q1 += acc[nt][0] * acc[nt][0] + acc[nt][1] * acc[nt][1];
        s2 += acc[nt][2] + acc[nt][3];
        q2 += acc[nt][2] * acc[nt][2] + acc[nt][3] * acc[nt][3];
    }

    float m1 = 0.f, rs1 = 1.f, m2 = 0.f, rs2 = 1.f;
    if (lng) {
#pragma unroll
        for (int off = 1; off < 4; off <<= 1) {
            s1 += __shfl_xor_sync(0xffffffffu, s1, off);
            q1 += __shfl_xor_sync(0xffffffffu, q1, off);
            s2 += __shfl_xor_sync(0xffffffffu, s2, off);
            q2 += __shfl_xor_sync(0xffffffffu, q2, off);
        }
        m1 = s1 * (1.0f / 128.0f);
        rs1 = rsqrtf(q1 * (1.0f / 128.0f) - m1 * m1 + 1e-5f);
        m2 = s2 * (1.0f / 128.0f);
        rs2 = rsqrtf(q2 * (1.0f / 128.0f) - m2 * m2 + 1e-5f);
    }

#pragma unroll
    for (int nt = 0; nt < 16; nt++) {
        int col = nt * 8 + cb;
        float o0 = acc[nt][0], o1 = acc[nt][1], o2 = acc[nt][2], o3 = acc[nt][3];
        if (lng) {
            float gx = lng[col], gy = lng[col + 1];
            float bx = lnb[col], by = lnb[col + 1];
            o0 = (o0 - m1) * rs1 * gx + bx;
            o1 = (o1 - m1) * rs1 * gy + by;
            o2 = (o2 - m2) * rs2 * gx + bx;
            o3 = (o3 - m2) * rs2 * gy + by;
        }
        if (ok1) *reinterpret_cast<float2*>(C + (size_t)r1 * 128 + col) = make_float2(o0, o1);
        if (ok2) *reinterpret_cast<float2*>(C + (size_t)r2 * 128 + col) = make_float2(o2, o3);
    }
}

// ---------------- host-side scan helper ----------------
static void run_scan(int* rp, const int* icnt, int* bsum, int n, int total)
{
    int nb = (n + 1023) / 1024;
    scan_block_kernel<<<nb, 1024>>>(icnt, n, rp, bsum);
    scan_small_kernel<<<1, 1024>>>(bsum, nb);
    scan_add_kernel<<<(n + 255) / 256, 256>>>(rp, bsum, n, total);
}

// ---------------- launch ----------------
extern "C" void kernel_launch(void* const* d_in, const int* in_sizes, int n_in,
                              void* d_out, int out_size)
{
    (void)in_sizes; (void)n_in; (void)out_size;
    const float* h0_bv = (const float*)d_in[0];
    const float* h0_lt = (const float*)d_in[1];
    const float* h0_cm = (const float*)d_in[2];
    const float* h0_dn = (const float*)d_in[3];
    const float* ft0 = (const float*)d_in[4];
    const float* ft1 = (const float*)d_in[5];
    const float* ft2 = (const float*)d_in[6];
    const float* ft3 = (const float*)d_in[7];
    const float* convW = (const float*)d_in[8];
    const float* convB = (const float*)d_in[9];
    const float* emlpW = (const float*)d_in[10];
    const float* emlpB = (const float*)d_in[11];
    const float* lng = (const float*)d_in[12];
    const float* lnb = (const float*)d_in[13];
    const int* src0 = (const int*)d_in[14];
    const int* dst0 = (const int*)d_in[15];
    const int* src1 = (const int*)d_in[16];
    const int* dst1 = (const int*)d_in[17];
    const int* src2 = (const int*)d_in[18];
    const int* dst2 = (const int*)d_in[19];
    const int* src3 = (const int*)d_in[20];
    const int* dst3 = (const int*)d_in[21];
    float* out = (float*)d_out;

    float* buf = nullptr;
    cudaGetSymbolAddress((void**)&buf, g_buf);

    float* mean_bv = buf + OF_MEANBV;
    float* agg2 = buf + OF_AGG2;
    float* agg3 = buf + OF_AGG3;
    float* fts0 = buf + OF_FTS0;
    float* fts1 = buf + OF_FTS1;
    float* fts2 = buf + OF_FTS2;
    float* fts3 = buf + OF_FTS3;
    float* z_lt = buf + OF_ZLT;
    float* z_cm = buf + OF_ZCM;
    float* bias_bv = buf + OF_BBV;
    float* bias_lt = buf + OF_BLT;
    float* bias_cm = buf + OF_BCM;
    unsigned short* ws = (unsigned short*)(buf + OF_WS);
    float* bcomb = buf + OF_BCOMB;

    int* icnt0 = (int*)(buf + OF_ICNT0);
    int* icnt1 = (int*)(buf + OF_ICNT1);
    int* icnt2 = (int*)(buf + OF_ICNT2);
    int* icnt3 = (int*)(buf + OF_ICNT3);
    int* rp0 = (int*)(buf + OF_RP0);
    int* rp1 = (int*)(buf + OF_RP1);
    int* rp2 = (int*)(buf + OF_RP2);
    int* rp3 = (int*)(buf + OF_RP3);
    int* cur0 = (int*)(buf + OF_CUR0);
    int* cur1 = (int*)(buf + OF_CUR1);
    int* cur2 = (int*)(buf + OF_CUR2);
    int* cur3 = (int*)(buf + OF_CUR3);
    int* ss0 = (int*)(buf + OF_SS0);
    int* ss1 = (int*)(buf + OF_SS1);
    int* ss2 = (int*)(buf + OF_SS2);
    int* ss3 = (int*)(buf + OF_SS3);
    int* bsum = (int*)(buf + OF_BSUM);

    // ---- layer-invariant precompute ----
    cudaMemsetAsync(buf + OF_FTS0, 0, (OF_FTS_END - OF_FTS0) * sizeof(float), 0);
    cudaMemsetAsync(buf + OF_ICNT0, 0, (OF_RP0 - OF_ICNT0) * sizeof(float), 0);

    cnt_ft_kernel<<<(E0_N + 255) / 256, 256>>>(dst0, ft0, icnt0, fts0, E0_N);
    cnt_ft_kernel<<<(E1_N + 255) / 256, 256>>>(dst1, ft1, icnt1, fts1, E1_N);
    cnt_ft_kernel<<<(E2_N + 255) / 256, 256>>>(dst2, ft2, icnt2, fts2, E2_N);
    cnt_ft_kernel<<<(E3_N + 255) / 256, 256>>>(dst3, ft3, icnt3, fts3, E3_N);

    run_scan(rp0, icnt0, bsum, N_BV, E0_N);
    run_scan(rp1, icnt1, bsum, N_BV, E1_N);
    run_scan(rp2, icnt2, bsum, N_LT, E2_N);
    run_scan(rp3, icnt3, bsum, N_CM, E3_N);

    cudaMemcpyAsync(cur0, rp0, N_BV * sizeof(int), cudaMemcpyDeviceToDevice, 0);
    cudaMemcpyAsync(cur1, rp1, N_BV * sizeof(int), cudaMemcpyDeviceToDevice, 0);
    cudaMemcpyAsync(cur2, rp2, N_LT * sizeof(int), cudaMemcpyDeviceToDevice, 0);
    cudaMemcpyAsync(cur3, rp3, N_CM * sizeof(int), cudaMemcpyDeviceToDevice, 0);

    scatter_kernel<<<(E0_N + 255) / 256, 256>>>(src0, dst0, cur0, ss0, E0_N);
    scatter_kernel<<<(E1_N + 255) / 256, 256>>>(src1, dst1, cur1, ss1, E1_N);
    scatter_kernel<<<(E2_N + 255) / 256, 256>>>(src2, dst2, cur2, ss2, E2_N);
    scatter_kernel<<<(E3_N + 255) / 256, 256>>>(src3, dst3, cur3, ss3, E3_N);

    bias_pre_kernel<<<N_BV, 128>>>(fts0, icnt0, emlpW + 0 * 2048, emlpB + 0,   bias_bv, 0);
    bias_pre_kernel<<<N_BV, 128>>>(fts1, icnt1, emlpW + 1 * 2048, emlpB + 128, bias_bv, 1);
    bias_pre_kernel<<<N_LT, 128>>>(fts2, icnt2, emlpW + 2 * 2048, emlpB + 256, bias_lt, 0);
    bias_pre_kernel<<<N_CM, 128>>>(fts3, icnt3, emlpW + 3 * 2048, emlpB + 384, bias_cm, 0);

    bprep_kernel<<<1, 256>>>(convB, bcomb);

    // ---- split + transpose weights into packed bf16 hi/lo chunks ----
    for (int l = 0; l < 2; l++) {
        const float* Wl = convW + (size_t)l * 4 * 32768;
        unsigned short* wsl = ws + (size_t)l * 28 * 8192;
        wsplit_kernel<<<4, 256>>>(Wl + 0 * 32768 + 16384, nullptr, wsl + 0 * 8192);   // W0_bot
        wsplit_kernel<<<4, 256>>>(Wl + 1 * 32768 + 16384, nullptr, wsl + 4 * 8192);   // W1_bot
        wsplit_kernel<<<4, 256>>>(Wl + 0 * 32768, Wl + 1 * 32768, wsl + 8 * 8192);    // wcomb (tops)
        wsplit_kernel<<<8, 256>>>(Wl + 2 * 32768, nullptr, wsl + 12 * 8192);          // W2 full 256
        wsplit_kernel<<<8, 256>>>(Wl + 3 * 32768, nullptr, wsl + 20 * 8192);          // W3 full 256
    }

    for (int l = 0; l < 2; l++) {
        const float* cur_bv = (l == 0) ? h0_bv : buf + OF_HBV;
        const float* cur_lt = (l == 0) ? h0_lt : buf + OF_HLT;
        const float* cur_cm = (l == 0) ? h0_cm : buf + OF_HCM;
        float* dst_bv = (l == 0) ? buf + OF_HBV : out;
        float* dst_lt = (l == 0) ? buf + OF_HLT : out + (size_t)N_BV * D;
        float* dst_cm = (l == 0) ? buf + OF_HCM : out + (size_t)(N_BV + N_LT) * D;
        unsigned short* wsl = ws + (size_t)l * 28 * 8192;

        // src-side transforms: z = h_src @ W_bot for e0 (lt->bv), e1 (cm->bv)
        gemm_tc<<<(N_LT + 127) / 128, 256>>>(cur_lt, nullptr, N_LT, wsl + 0 * 8192, 4,
                                             nullptr, nullptr, nullptr, nullptr, nullptr, z_lt);
        gemm_tc<<<(N_CM + 127) / 128, 256>>>(cur_cm, nullptr, N_CM, wsl + 4 * 8192, 4,
                                             nullptr, nullptr, nullptr, nullptr, nullptr, z_cm);

        // CSR mean aggregations
        csr_mean2_kernel<<<(N_BV * 32 + 255) / 256, 256>>>(
            rp0, ss0, z_lt, rp1, ss1, z_cm, mean_bv, N_BV);
        if (l == 0) {
            csr_mean1_kernel<<<(N_LT * 32 + 255) / 256, 256>>>(rp2, ss2, h0_dn, agg2, N_LT);
        } else {
            fill_cond_kernel<<<N_LT, 128>>>(rp2, lnb + 384, agg2, N_LT);
        }
        csr_mean1_kernel<<<(N_CM * 32 + 255) / 256, 256>>>(rp3, ss3, cur_bv, agg3, N_CM);

        // fused conv + epilogue + LayerNorm per dst type
        gemm_tc<<<(N_BV + 127) / 128, 256>>>(cur_bv, nullptr, N_BV, wsl + 8 * 8192, 4,
                                             bcomb + l * 128, mean_bv, bias_bv,
                                             lng + 0, lnb + 0, dst_bv);
        gemm_tc<<<(N_LT + 127) / 128, 256>>>(cur_lt, agg2, N_LT, wsl + 12 * 8192, 8,
                                             convB + (l * 4 + 2) * 128, bias_lt, nullptr,
                                             lng + 128, lnb + 128, dst_lt);
        gemm_tc<<<(N_CM + 127) / 128, 256>>>(cur_cm, agg3, N_CM, wsl + 20 * 8192, 8,
                                             convB + (l * 4 + 3) * 128, bias_cm, nullptr,
                                             lng + 256, lnb + 256, dst_cm);
    }

    // dn output: LN(zeros) = ln_b[3] broadcast
    fill_rows_kernel<<<(int)(((size_t)N_DN * D + 255) / 256), 256>>>(
        out + (size_t)(N_BV + N_LT + N_CM) * D, lnb + 384, (size_t)N_DN * D);
}

// round 5
// speedup vs baseline: 2.3256x; 1.3243x over previous
#include <cuda_runtime.h>
#include <cuda_bf16.h>
#include <cstdint>
#include <cstddef>

#define D 128
#define N_BV 100000
#define N_LT 20000
#define N_CM 2000
#define N_DN 100000
#define E0_N 600000
#define E1_N 200000
#define E2_N 500000
#define E3_N 200000

// ---------------- scratch layout ----------------
constexpr size_t AL(size_t x) { return (x + 31) & ~size_t(31); }
constexpr size_t WS_USHORTS = 2 * 28 * 8192;
constexpr size_t WS_FLOATS  = WS_USHORTS / 2;

constexpr size_t OF_MEANBV = 0;
constexpr size_t OF_AGG2   = AL(OF_MEANBV + (size_t)N_BV * D);
constexpr size_t OF_AGG3   = AL(OF_AGG2 + (size_t)N_LT * D);
constexpr size_t OF_FTS0   = AL(OF_AGG3 + (size_t)N_CM * D);
constexpr size_t OF_FTS1   = AL(OF_FTS0 + (size_t)N_BV * 16);
constexpr size_t OF_FTS2   = AL(OF_FTS1 + (size_t)N_BV * 16);
constexpr size_t OF_FTS3   = AL(OF_FTS2 + (size_t)N_LT * 16);
constexpr size_t OF_FTS_END= AL(OF_FTS3 + (size_t)N_CM * 16);
constexpr size_t OF_HBV    = OF_FTS_END;
constexpr size_t OF_HLT    = AL(OF_HBV + (size_t)N_BV * D);
constexpr size_t OF_HCM    = AL(OF_HLT + (size_t)N_LT * D);
constexpr size_t OF_ZLT    = AL(OF_HCM + (size_t)N_CM * D);
constexpr size_t OF_ZCM    = AL(OF_ZLT + (size_t)N_LT * D);
constexpr size_t OF_BBV    = AL(OF_ZCM + (size_t)N_CM * D);
constexpr size_t OF_BLT    = AL(OF_BBV + (size_t)N_BV * D);
constexpr size_t OF_BCM    = AL(OF_BLT + (size_t)N_LT * D);
constexpr size_t OF_WS     = AL(OF_BCM + (size_t)N_CM * D);
constexpr size_t OF_BCOMB  = AL(OF_WS + WS_FLOATS);
// ---- int region ----
constexpr size_t OF_ICNT0  = AL(OF_BCOMB + 256);
constexpr size_t OF_ICNT1  = AL(OF_ICNT0 + N_BV);
constexpr size_t OF_ICNT2  = AL(OF_ICNT1 + N_BV);
constexpr size_t OF_ICNT3  = AL(OF_ICNT2 + N_LT);
constexpr size_t OF_ICNT_END = AL(OF_ICNT3 + N_CM);
constexpr size_t OF_RP0    = OF_ICNT_END;
constexpr size_t OF_RP1    = AL(OF_RP0 + N_BV + 1);
constexpr size_t OF_RP2    = AL(OF_RP1 + N_BV + 1);
constexpr size_t OF_RP3    = AL(OF_RP2 + N_LT + 1);
constexpr size_t OF_CUR0   = AL(OF_RP3 + N_CM + 1);
constexpr size_t OF_CUR1   = AL(OF_CUR0 + N_BV);
constexpr size_t OF_CUR2   = AL(OF_CUR1 + N_BV);
constexpr size_t OF_CUR3   = AL(OF_CUR2 + N_LT);
constexpr size_t OF_SS0    = AL(OF_CUR3 + N_CM);
constexpr size_t OF_SS1    = AL(OF_SS0 + E0_N);
constexpr size_t OF_SS2    = AL(OF_SS1 + E1_N);
constexpr size_t OF_SS3    = AL(OF_SS2 + E2_N);
constexpr size_t OF_BSUM0  = AL(OF_SS3 + E3_N);
constexpr size_t OF_BSUM1  = AL(OF_BSUM0 + 128);
constexpr size_t OF_BSUM2  = AL(OF_BSUM1 + 128);
constexpr size_t OF_BSUM3  = AL(OF_BSUM2 + 128);
constexpr size_t SCRATCH_TOTAL = OF_BSUM3 + 128;

__device__ __align__(128) float g_buf[SCRATCH_TOTAL];

// ---------------- block-range dispatch constants ----------------
constexpr int CB0 = (E0_N + 255) / 256, CB1 = (E1_N + 255) / 256,
              CB2 = (E2_N + 255) / 256, CB3 = (E3_N + 255) / 256;
constexpr int NB0 = (N_BV + 1023) / 1024, NB1 = NB0,
              NB2 = (N_LT + 1023) / 1024, NB3 = (N_CM + 1023) / 1024;
constexpr int AB0 = (N_BV + 255) / 256, AB1 = AB0,
              AB2 = (N_LT + 255) / 256, AB3 = (N_CM + 255) / 256;
constexpr int GB_BV = (N_BV + 127) / 128, GB_LT = (N_LT + 127) / 128,
              GB_CM = (N_CM + 127) / 128;
constexpr int CSR_WARPS = N_BV + N_LT + N_CM;

// ---------------- helpers ----------------
__device__ __forceinline__ void red_add_v4(float* p, float4 v) {
    asm volatile("red.global.add.v4.f32 [%0], {%1, %2, %3, %4};"
                 :: "l"(p), "f"(v.x), "f"(v.y), "f"(v.z), "f"(v.w)
                 : "memory");
}
__device__ __forceinline__ unsigned short f2bf(float x) {
    __nv_bfloat16 h = __float2bfloat16(x);
    return *reinterpret_cast<unsigned short*>(&h);
}
__device__ __forceinline__ float bf2f(unsigned short u) {
    __nv_bfloat16 h;
    *reinterpret_cast<unsigned short*>(&h) = u;
    return __bfloat162float(h);
}
#define MMA_BF16(d, a0, a1, a2, a3, b0, b1) \
    asm volatile("mma.sync.aligned.m16n8k16.row.col.f32.bf16.bf16.f32 " \
                 "{%0,%1,%2,%3},{%4,%5,%6,%7},{%8,%9},{%0,%1,%2,%3};" \
                 : "+f"(d[0]), "+f"(d[1]), "+f"(d[2]), "+f"(d[3]) \
                 : "r"(a0), "r"(a1), "r"(a2), "r"(a3), "r"(b0), "r"(b1))

// ================= fused preprocessing kernels =================

__device__ __forceinline__ void cnt_ft_body(int i, const int* __restrict__ dst,
                                            const float* __restrict__ ft,
                                            int* __restrict__ icnt, float* __restrict__ fts, int E)
{
    if (i >= E) return;
    int d = dst[i];
    atomicAdd(icnt + d, 1);
    const float4* f = reinterpret_cast<const float4*>(ft) + (size_t)i * 4;
    float* o = fts + (size_t)d * 16;
    red_add_v4(o + 0,  f[0]);
    red_add_v4(o + 4,  f[1]);
    red_add_v4(o + 8,  f[2]);
    red_add_v4(o + 12, f[3]);
}

__global__ void cnt_ft_all(const int* dst0, const float* ft0, int* icnt0, float* fts0,
                           const int* dst1, const float* ft1, int* icnt1, float* fts1,
                           const int* dst2, const float* ft2, int* icnt2, float* fts2,
                           const int* dst3, const float* ft3, int* icnt3, float* fts3)
{
    int bx = blockIdx.x, tid = threadIdx.x;
    if (bx < CB0)                 cnt_ft_body(bx * 256 + tid, dst0, ft0, icnt0, fts0, E0_N);
    else if (bx < CB0 + CB1)      cnt_ft_body((bx - CB0) * 256 + tid, dst1, ft1, icnt1, fts1, E1_N);
    else if (bx < CB0 + CB1 + CB2) cnt_ft_body((bx - CB0 - CB1) * 256 + tid, dst2, ft2, icnt2, fts2, E2_N);
    else                          cnt_ft_body((bx - CB0 - CB1 - CB2) * 256 + tid, dst3, ft3, icnt3, fts3, E3_N);
}

__device__ __forceinline__ void scatter_body(int i, const int* __restrict__ src,
                                             const int* __restrict__ dst,
                                             int* __restrict__ cur, int* __restrict__ ss, int E)
{
    if (i >= E) return;
    int d = dst[i];
    int p = atomicAdd(cur + d, 1);
    ss[p] = src[i];
}

__global__ void scatter_all(const int* s0, const int* d0, int* c0, int* x0,
                            const int* s1, const int* d1, int* c1, int* x1,
                            const int* s2, const int* d2, int* c2, int* x2,
                            const int* s3, const int* d3, int* c3, int* x3)
{
    int bx = blockIdx.x, tid = threadIdx.x;
    if (bx < CB0)                 scatter_body(bx * 256 + tid, s0, d0, c0, x0, E0_N);
    else if (bx < CB0 + CB1)      scatter_body((bx - CB0) * 256 + tid, s1, d1, c1, x1, E1_N);
    else if (bx < CB0 + CB1 + CB2) scatter_body((bx - CB0 - CB1) * 256 + tid, s2, d2, c2, x2, E2_N);
    else                          scatter_body((bx - CB0 - CB1 - CB2) * 256 + tid, s3, d3, c3, x3, E3_N);
}

// ---------------- batched scans ----------------
__global__ void scan_block_all(const int* i0, int* r0, int* b0,
                               const int* i1, int* r1, int* b1,
                               const int* i2, int* r2, int* b2,
                               const int* i3, int* r3, int* b3)
{
    __shared__ int sh[1024];
    int bx = blockIdx.x;
    const int* in; int* outp; int* bs; int n; int lb;
    if (bx < NB0)                  { in = i0; outp = r0; bs = b0; n = N_BV; lb = bx; }
    else if (bx < NB0 + NB1)       { in = i1; outp = r1; bs = b1; n = N_BV; lb = bx - NB0; }
    else if (bx < NB0 + NB1 + NB2) { in = i2; outp = r2; bs = b2; n = N_LT; lb = bx - NB0 - NB1; }
    else                           { in = i3; outp = r3; bs = b3; n = N_CM; lb = bx - NB0 - NB1 - NB2; }
    int i = lb * 1024 + threadIdx.x;
    int v = (i < n) ? in[i] : 0;
    sh[threadIdx.x] = v;
    __syncthreads();
    for (int off = 1; off < 1024; off <<= 1) {
        int t = (threadIdx.x >= (unsigned)off) ? sh[threadIdx.x - off] : 0;
        __syncthreads();
        sh[threadIdx.x] += t;
        __syncthreads();
    }
    if (i < n) outp[i] = sh[threadIdx.x] - v;
    if (threadIdx.x == 1023) bs[lb] = sh[1023];
}

__global__ void scan_small_all(int* b0, int* b1, int* b2, int* b3)
{
    __shared__ int sh[1024];
    int* bp[4] = {b0, b1, b2, b3};
    const int nbv[4] = {NB0, NB1, NB2, NB3};
    for (int t = 0; t < 4; t++) {
        int n = nbv[t];
        int v = ((int)threadIdx.x < n) ? bp[t][threadIdx.x] : 0;
        sh[threadIdx.x] = v;
        __syncthreads();
        for (int off = 1; off < 1024; off <<= 1) {
            int x = (threadIdx.x >= (unsigned)off) ? sh[threadIdx.x - off] : 0;
            __syncthreads();
            sh[threadIdx.x] += x;
            __syncthreads();
        }
        if ((int)threadIdx.x < n) bp[t][threadIdx.x] = sh[threadIdx.x] - v;
        __syncthreads();
    }
}

__device__ __forceinline__ void scan_add_body(int lb, int tid, int* __restrict__ rp,
                                              int* __restrict__ cur, const int* __restrict__ bs,
                                              int n, int total)
{
    int i = lb * 256 + tid;
    if (i < n) {
        int v = rp[i] + bs[i >> 10];
        rp[i] = v;
        cur[i] = v;
    }
    if (lb == 0 && tid == 0) rp[n] = total;
}

__global__ void scan_add_all(int* r0, int* c0, const int* b0,
                             int* r1, int* c1, const int* b1,
                             int* r2, int* c2, const int* b2,
                             int* r3, int* c3, const int* b3)
{
    int bx = blockIdx.x, tid = threadIdx.x;
    if (bx < AB0)                  scan_add_body(bx, tid, r0, c0, b0, N_BV, E0_N);
    else if (bx < AB0 + AB1)       scan_add_body(bx - AB0, tid, r1, c1, b1, N_BV, E1_N);
    else if (bx < AB0 + AB1 + AB2) scan_add_body(bx - AB0 - AB1, tid, r2, c2, b2, N_LT, E2_N);
    else                           scan_add_body(bx - AB0 - AB1 - AB2, tid, r3, c3, b3, N_CM, E3_N);
}

// ---------------- fused edge-bias (all three dst tables) ----------------
__global__ void bias_all(const float* __restrict__ fts0, const int* __restrict__ icnt0,
                         const float* __restrict__ fts1, const int* __restrict__ icnt1,
                         const float* __restrict__ fts2, const int* __restrict__ icnt2,
                         const float* __restrict__ fts3, const int* __restrict__ icnt3,
                         const float* __restrict__ emlpW, const float* __restrict__ emlpB,
                         float* __restrict__ bias_bv, float* __restrict__ bias_lt,
                         float* __restrict__ bias_cm)
{
    int row = blockIdx.x;
    int c = threadIdx.x;
    __shared__ float f0[16], f1[16];
    if (row < N_BV) {
        if (c < 16) f0[c] = fts0[(size_t)row * 16 + c];
        else if (c >= 32 && c < 48) f1[c - 32] = fts1[(size_t)row * 16 + (c - 32)];
        __syncthreads();
        int c0 = icnt0[row], c1 = icnt1[row];
        float i0 = (c0 > 0) ? 1.0f / (float)c0 : 0.0f;
        float i1 = (c1 > 0) ? 1.0f / (float)c1 : 0.0f;
        float a0 = 0.0f, a1 = 0.0f;
#pragma unroll
        for (int j = 0; j < 16; j++) {
            a0 = fmaf(f0[j], emlpW[j * 128 + c], a0);
            a1 = fmaf(f1[j], emlpW[2048 + j * 128 + c], a1);
        }
        float a = a0 * i0 + a1 * i1;
        if (c0 > 0) a += emlpB[c];
        if (c1 > 0) a += emlpB[128 + c];
        bias_bv[(size_t)row * 128 + c] = a;
    } else {
        const float* fts; const int* icnt; const float* W; const float* bml;
        float* outp; int r;
        if (row < N_BV + N_LT) {
            r = row - N_BV; fts = fts2; icnt = icnt2;
            W = emlpW + 2 * 2048; bml = emlpB + 256; outp = bias_lt;
        } else {
            r = row - N_BV - N_LT; fts = fts3; icnt = icnt3;
            W = emlpW + 3 * 2048; bml = emlpB + 384; outp = bias_cm;
        }
        if (c < 16) f0[c] = fts[(size_t)r * 16 + c];
        __syncthreads();
        int cv = icnt[r];
        float inv = (cv > 0) ? 1.0f / (float)cv : 0.0f;
        float a = 0.0f;
#pragma unroll
        for (int j = 0; j < 16; j++) a = fmaf(f0[j], W[j * 128 + c], a);
        a *= inv;
        if (cv > 0) a += bml[c];
        outp[(size_t)r * 128 + c] = a;
    }
}

// ---------------- weight split (all chunks, both layers) + bcomb ----------------
__global__ void wsplit_all(const float* __restrict__ convW, const float* __restrict__ convB,
                           unsigned short* __restrict__ ws, float* __restrict__ bcomb)
{
    int bx = blockIdx.x;
    if (bx == 56) {
        int idx = threadIdx.x;
        if (idx < 256) {
            int l = idx >> 7, c = idx & 127;
            bcomb[idx] = convB[(l * 4 + 0) * 128 + c] + convB[(l * 4 + 1) * 128 + c];
        }
        return;
    }
    int l = bx / 28, c = bx % 28;
    const float* Wl = convW + (size_t)l * 4 * 32768;
    unsigned short* wsl = ws + (size_t)l * 28 * 8192;
    const float* W; const float* W2 = nullptr; int chunk; unsigned short* o;
    if (c < 4)       { W = Wl + 16384;             chunk = c;      o = wsl; }
    else if (c < 8)  { W = Wl + 32768 + 16384;     chunk = c - 4;  o = wsl + 4 * 8192; }
    else if (c < 12) { W = Wl; W2 = Wl + 32768;    chunk = c - 8;  o = wsl + 8 * 8192; }
    else if (c < 20) { W = Wl + 2 * 32768;         chunk = c - 12; o = wsl + 12 * 8192; }
    else             { W = Wl + 3 * 32768;         chunk = c - 20; o = wsl + 20 * 8192; }
    int k0 = chunk * 32;
    unsigned short* op = o + (size_t)chunk * 8192;
#pragma unroll
    for (int t = 0; t < 16; t++) {
        int e = threadIdx.x + t * 256;
        int k = e >> 7;
        int n = e & 127;
        float w = W[(size_t)(k0 + k) * 128 + n];
        if (W2) w += W2[(size_t)(k0 + k) * 128 + n];
        unsigned short hi = f2bf(w);
        unsigned short lo = f2bf(w - bf2f(hi));
        op[n * 32 + k] = hi;
        op[4096 + n * 32 + k] = lo;
    }
}

// ---------------- fused CSR aggregation (bv mean2 + lt agg + cm agg) ----------------
__device__ __forceinline__ float4 csr_gather_mean(const int* __restrict__ rp,
                                                  const int* __restrict__ ss,
                                                  const float* __restrict__ X,
                                                  int w, int lane)
{
    int b = rp[w], e = rp[w + 1];
    float4 acc = make_float4(0.f, 0.f, 0.f, 0.f);
    int j = b;
    for (; j + 2 <= e; j += 2) {
        int s0 = __ldg(ss + j), s1 = __ldg(ss + j + 1);
        float4 v0 = __ldg(reinterpret_cast<const float4*>(X + (size_t)s0 * 128) + lane);
        float4 v1 = __ldg(reinterpret_cast<const float4*>(X + (size_t)s1 * 128) + lane);
        acc.x += v0.x + v1.x; acc.y += v0.y + v1.y;
        acc.z += v0.z + v1.z; acc.w += v0.w + v1.w;
    }
    if (j < e) {
        int s0 = __ldg(ss + j);
        float4 v0 = __ldg(reinterpret_cast<const float4*>(X + (size_t)s0 * 128) + lane);
        acc.x += v0.x; acc.y += v0.y; acc.z += v0.z; acc.w += v0.w;
    }
    float inv = (e > b) ? 1.0f / (float)(e - b) : 0.0f;
    acc.x *= inv; acc.y *= inv; acc.z *= inv; acc.w *= inv;
    return acc;
}

__global__ void csr_all_kernel(
    const int* __restrict__ rp0, const int* __restrict__ ss0, const float* __restrict__ X0,
    const int* __restrict__ rp1, const int* __restrict__ ss1, const float* __restrict__ X1,
    float* __restrict__ mean_bv,
    const int* __restrict__ rp2, const int* __restrict__ ss2, const float* __restrict__ X2,
    float* __restrict__ agg2, const float* __restrict__ lnb3, int l2mode,
    const int* __restrict__ rp3, const int* __restrict__ ss3, const float* __restrict__ X3,
    float* __restrict__ agg3)
{
    int gw = (int)((blockIdx.x * blockDim.x + threadIdx.x) >> 5);
    int lane = threadIdx.x & 31;
    if (gw < N_BV) {
        float4 a = csr_gather_mean(rp0, ss0, X0, gw, lane);
        float4 b = csr_gather_mean(rp1, ss1, X1, gw, lane);
        a.x += b.x; a.y += b.y; a.z += b.z; a.w += b.w;
        reinterpret_cast<float4*>(mean_bv + (size_t)gw * 128)[lane] = a;
    } else if (gw < N_BV + N_LT) {
        int w = gw - N_BV;
        if (!l2mode) {
            float4 a = csr_gather_mean(rp2, ss2, X2, w, lane);
            reinterpret_cast<float4*>(agg2 + (size_t)w * 128)[lane] = a;
        } else {
            bool nz = rp2[w + 1] > rp2[w];
            float4 v = make_float4(0.f, 0.f, 0.f, 0.f);
            if (nz) v = *reinterpret_cast<const float4*>(lnb3 + lane * 4);
            reinterpret_cast<float4*>(agg2 + (size_t)w * 128)[lane] = v;
        }
    } else if (gw < CSR_WARPS) {
        int w = gw - N_BV - N_LT;
        float4 a = csr_gather_mean(rp3, ss3, X3, w, lane);
        reinterpret_cast<float4*>(agg3 + (size_t)w * 128)[lane] = a;
    }
}

// ---------------- dn output fill ----------------
__global__ void fill_rows_kernel(float* __restrict__ dest, const float* __restrict__ b, size_t total)
{
    size_t i = (size_t)blockIdx.x * blockDim.x + threadIdx.x;
    if (i < total) dest[i] = b[i & 127];
}

// ---------------- tensor-core split-bf16 GEMM + fused epilogue (multi-problem) ----------------
struct GP {
    const float* A1; const float* A2; int M;
    const unsigned short* wsp; int Kc;
    const float* bvec; const float* add1; const float* add2;
    const float* lng; const float* lnb;
    float* C;
};

__device__ void gemm_body(int blk, const GP& p)
{
    __shared__ unsigned short Ah[128][40], Alo[128][40];
    __shared__ unsigned short Bh[128][40], Bl[128][40];
    int tid = threadIdx.x;
    int wid = tid >> 5, lane = tid & 31;
    int row0 = blk * 128;
    int M = p.M;

    float acc[16][4];
#pragma unroll
    for (int i = 0; i < 16; i++)
#pragma unroll
        for (int j = 0; j < 4; j++) acc[i][j] = 0.0f;

    for (int kc = 0; kc < p.Kc; kc++) {
        const float* Asrc = (kc < 4) ? p.A1 : p.A2;
        int kk = (kc & 3) * 32;
#pragma unroll
        for (int t = 0; t < 4; t++) {
            int i = tid + t * 256;
            int r = i >> 3;
            int kq = i & 7;
            int gr = row0 + r;
            float4 v = make_float4(0.f, 0.f, 0.f, 0.f);
            if (gr < M) v = *reinterpret_cast<const float4*>(Asrc + (size_t)gr * 128 + kk + kq * 4);
            unsigned short h0 = f2bf(v.x), h1 = f2bf(v.y), h2 = f2bf(v.z), h3 = f2bf(v.w);
            unsigned short l0 = f2bf(v.x - bf2f(h0)), l1 = f2bf(v.y - bf2f(h1));
            unsigned short l2 = f2bf(v.z - bf2f(h2)), l3 = f2bf(v.w - bf2f(h3));
            *reinterpret_cast<uint2*>(&Ah[r][kq * 4]) =
                make_uint2((uint32_t)h0 | ((uint32_t)h1 << 16), (uint32_t)h2 | ((uint32_t)h3 << 16));
            *reinterpret_cast<uint2*>(&Alo[r][kq * 4]) =
                make_uint2((uint32_t)l0 | ((uint32_t)l1 << 16), (uint32_t)l2 | ((uint32_t)l3 << 16));
        }
        const uint4* wp = reinterpret_cast<const uint4*>(p.wsp + (size_t)kc * 8192);
#pragma unroll
        for (int t = 0; t < 2; t++) {
            int i = tid + t * 256;
            int n = i >> 2;
            int kq = i & 3;
            *reinterpret_cast<uint4*>(&Bh[n][kq * 8]) = wp[i];
            *reinterpret_cast<uint4*>(&Bl[n][kq * 8]) = wp[512 + i];
        }
        __syncthreads();
#pragma unroll
        for (int ks = 0; ks < 2; ks++) {
            int ac = ks * 16 + (lane & 3) * 2;
            int ar = wid * 16 + (lane >> 2);
            uint32_t ah0 = *reinterpret_cast<const uint32_t*>(&Ah[ar][ac]);
            uint32_t ah1 = *reinterpret_cast<const uint32_t*>(&Ah[ar + 8][ac]);
            uint32_t ah2 = *reinterpret_cast<const uint32_t*>(&Ah[ar][ac + 8]);
            uint32_t ah3 = *reinterpret_cast<const uint32_t*>(&Ah[ar + 8][ac + 8]);
            uint32_t al0 = *reinterpret_cast<const uint32_t*>(&Alo[ar][ac]);
            uint32_t al1 = *reinterpret_cast<const uint32_t*>(&Alo[ar + 8][ac]);
            uint32_t al2 = *reinterpret_cast<const uint32_t*>(&Alo[ar][ac + 8]);
            uint32_t al3 = *reinterpret_cast<const uint32_t*>(&Alo[ar + 8][ac + 8]);
#pragma unroll
            for (int nt = 0; nt < 16; nt++) {
                int bn = nt * 8 + (lane >> 2);
                uint32_t bh0 = *reinterpret_cast<const uint32_t*>(&Bh[bn][ac]);
                uint32_t bh1 = *reinterpret_cast<const uint32_t*>(&Bh[bn][ac + 8]);
                uint32_t bl0 = *reinterpret_cast<const uint32_t*>(&Bl[bn][ac]);
                uint32_t bl1 = *reinterpret_cast<const uint32_t*>(&Bl[bn][ac + 8]);
                MMA_BF16(acc[nt], ah0, ah1, ah2, ah3, bh0, bh1);
                MMA_BF16(acc[nt], ah0, ah1, ah2, ah3, bl0, bl1);
                MMA_BF16(acc[nt], al0, al1, al2, al3, bh0, bh1);
            }
        }
        __syncthreads();
    }

    int r1 = row0 + wid * 16 + (lane >> 2);
    int r2 = r1 + 8;
    int cb = (lane & 3) * 2;
    bool ok1 = r1 < M, ok2 = r2 < M;

    float s1 = 0.f, q1 = 0.f, s2 = 0.f, q2 = 0.f;
#pragma unroll
    for (int nt = 0; nt < 16; nt++) {
        int col = nt * 8 + cb;
        if (p.bvec) {
            float bx = p.bvec[col], by = p.bvec[col + 1];
            acc[nt][0] += bx; acc[nt][1] += by;
            acc[nt][2] += bx; acc[nt][3] += by;
        }
        if (p.add1) {
            if (ok1) {
                float2 q = *reinterpret_cast<const float2*>(p.add1 + (size_t)r1 * 128 + col);
                acc[nt][0] += q.x; acc[nt][1] += q.y;
            }
            if (ok2) {
                float2 q = *reinterpret_cast<const float2*>(p.add1 + (size_t)r2 * 128 + col);
                acc[nt][2] += q.x; acc[nt][3] += q.y;
            }
        }
        if (p.add2) {
            if (ok1) {
                float2 q = *reinterpret_cast<const float2*>(p.add2 + (size_t)r1 * 128 + col);
                acc[nt][0] += q.x; acc[nt][1] += q.y;
            }
            if (ok2) {
                float2 q = *reinterpret_cast<const float2*>(p.add2 + (size_t)r2 * 128 + col);
                acc[nt][2] += q.x; acc[nt][3] += q.y;
            }
        }
        s1 += acc[nt][0] + acc[nt][1];
        q1 += acc[nt][0] * acc[nt][0] + acc[nt][1] * acc[nt][1];
        s2 += acc[nt][2] + acc[nt][3];
        q2 += acc[nt][2] * acc[nt][2] + acc[nt][3] * acc[nt][3];
    }

    float m1 = 0.f, rs1 = 1.f, m2 = 0.f, rs2 = 1.f;
    if (p.lng) {
#pragma unroll
        for (int off = 1; off < 4; off <<= 1) {
            s1 += __shfl_xor_sync(0xffffffffu, s1, off);
            q1 += __shfl_xor_sync(0xffffffffu, q1, off);
            s2 += __shfl_xor_sync(0xffffffffu, s2, off);
            q2 += __shfl_xor_sync(0xffffffffu, q2, off);
        }
        m1 = s1 * (1.0f / 128.0f);
        rs1 = rsqrtf(q1 * (1.0f / 128.0f) - m1 * m1 + 1e-5f);
        m2 = s2 * (1.0f / 128.0f);
        rs2 = rsqrtf(q2 * (1.0f / 128.0f) - m2 * m2 + 1e-5f);
    }

#pragma unroll
    for (int nt = 0; nt < 16; nt++) {
        int col = nt * 8 + cb;
        float o0 = acc[nt][0], o1 = acc[nt][1], o2 = acc[nt][2], o3 = acc[nt][3];
        if (p.lng) {
            float gx = p.lng[col], gy = p.lng[col + 1];
            float bx = p.lnb[col], by = p.lnb[col + 1];
            o0 = (o0 - m1) * rs1 * gx + bx;
            o1 = (o1 - m1) * rs1 * gy + by;
            o2 = (o2 - m2) * rs2 * gx + bx;
            o3 = (o3 - m2) * rs2 * gy + by;
        }
        if (ok1) *reinterpret_cast<float2*>(p.C + (size_t)r1 * 128 + col) = make_float2(o0, o1);
        if (ok2) *reinterpret_cast<float2*>(p.C + (size_t)r2 * 128 + col) = make_float2(o2, o3);
    }
}

__global__ __launch_bounds__(256, 2) void gemm3_kernel(GP p0, GP p1, GP p2, int nb0, int nb1)
{
    int bx = blockIdx.x;
    if (bx < nb0) gemm_body(bx, p0);
    else if (bx < nb0 + nb1) gemm_body(bx - nb0, p1);
    else gemm_body(bx - nb0 - nb1, p2);
}

// ---------------- launch ----------------
extern "C" void kernel_launch(void* const* d_in, const int* in_sizes, int n_in,
                              void* d_out, int out_size)
{
    (void)in_sizes; (void)n_in; (void)out_size;
    const float* h0_bv = (const float*)d_in[0];
    const float* h0_lt = (const float*)d_in[1];
    const float* h0_cm = (const float*)d_in[2];
    const float* h0_dn = (const float*)d_in[3];
    const float* ft0 = (const float*)d_in[4];
    const float* ft1 = (const float*)d_in[5];
    const float* ft2 = (const float*)d_in[6];
    const float* ft3 = (const float*)d_in[7];
    const float* convW = (const float*)d_in[8];
    const float* convB = (const float*)d_in[9];
    const float* emlpW = (const float*)d_in[10];
    const float* emlpB = (const float*)d_in[11];
    const float* lng = (const float*)d_in[12];
    const float* lnb = (const float*)d_in[13];
    const int* src0 = (const int*)d_in[14];
    const int* dst0 = (const int*)d_in[15];
    const int* src1 = (const int*)d_in[16];
    const int* dst1 = (const int*)d_in[17];
    const int* src2 = (const int*)d_in[18];
    const int* dst2 = (const int*)d_in[19];
    const int* src3 = (const int*)d_in[20];
    const int* dst3 = (const int*)d_in[21];
    float* out = (float*)d_out;

    float* buf = nullptr;
    cudaGetSymbolAddress((void**)&buf, g_buf);

    float* mean_bv = buf + OF_MEANBV;
    float* agg2 = buf + OF_AGG2;
    float* agg3 = buf + OF_AGG3;
    float* fts0 = buf + OF_FTS0;
    float* fts1 = buf + OF_FTS1;
    float* fts2 = buf + OF_FTS2;
    float* fts3 = buf + OF_FTS3;
    float* z_lt = buf + OF_ZLT;
    float* z_cm = buf + OF_ZCM;
    float* bias_bv = buf + OF_BBV;
    float* bias_lt = buf + OF_BLT;
    float* bias_cm = buf + OF_BCM;
    unsigned short* ws = (unsigned short*)(buf + OF_WS);
    float* bcomb = buf + OF_BCOMB;

    int* icnt0 = (int*)(buf + OF_ICNT0);
    int* icnt1 = (int*)(buf + OF_ICNT1);
    int* icnt2 = (int*)(buf + OF_ICNT2);
    int* icnt3 = (int*)(buf + OF_ICNT3);
    int* rp0 = (int*)(buf + OF_RP0);
    int* rp1 = (int*)(buf + OF_RP1);
    int* rp2 = (int*)(buf + OF_RP2);
    int* rp3 = (int*)(buf + OF_RP3);
    int* cur0 = (int*)(buf + OF_CUR0);
    int* cur1 = (int*)(buf + OF_CUR1);
    int* cur2 = (int*)(buf + OF_CUR2);
    int* cur3 = (int*)(buf + OF_CUR3);
    int* ss0 = (int*)(buf + OF_SS0);
    int* ss1 = (int*)(buf + OF_SS1);
    int* ss2 = (int*)(buf + OF_SS2);
    int* ss3 = (int*)(buf + OF_SS3);
    int* bs0 = (int*)(buf + OF_BSUM0);
    int* bs1 = (int*)(buf + OF_BSUM1);
    int* bs2 = (int*)(buf + OF_BSUM2);
    int* bs3 = (int*)(buf + OF_BSUM3);

    float* HBV = buf + OF_HBV;
    float* HLT = buf + OF_HLT;
    float* HCM = buf + OF_HCM;
    float* out_bv = out;
    float* out_lt = out + (size_t)N_BV * D;
    float* out_cm = out + (size_t)(N_BV + N_LT) * D;
    float* out_dn = out + (size_t)(N_BV + N_LT + N_CM) * D;

    unsigned short* ws0 = ws;
    unsigned short* ws1 = ws + (size_t)28 * 8192;

    // ===== preprocessing (all on stream 0) =====
    cudaMemsetAsync(buf + OF_FTS0, 0, (OF_FTS_END - OF_FTS0) * sizeof(float), 0);
    cudaMemsetAsync(buf + OF_ICNT0, 0, (OF_ICNT_END - OF_ICNT0) * sizeof(float), 0);

    fill_rows_kernel<<<(int)(((size_t)N_DN * D + 255) / 256), 256>>>(
        out_dn, lnb + 384, (size_t)N_DN * D);

    cnt_ft_all<<<CB0 + CB1 + CB2 + CB3, 256>>>(dst0, ft0, icnt0, fts0,
                                               dst1, ft1, icnt1, fts1,
                                               dst2, ft2, icnt2, fts2,
                                               dst3, ft3, icnt3, fts3);

    bias_all<<<N_BV + N_LT + N_CM, 128>>>(fts0, icnt0, fts1, icnt1, fts2, icnt2, fts3, icnt3,
                                          emlpW, emlpB, bias_bv, bias_lt, bias_cm);

    scan_block_all<<<NB0 + NB1 + NB2 + NB3, 1024>>>(icnt0, rp0, bs0, icnt1, rp1, bs1,
                                                    icnt2, rp2, bs2, icnt3, rp3, bs3);
    scan_small_all<<<1, 1024>>>(bs0, bs1, bs2, bs3);
    scan_add_all<<<AB0 + AB1 + AB2 + AB3, 256>>>(rp0, cur0, bs0, rp1, cur1, bs1,
                                                 rp2, cur2, bs2, rp3, cur3, bs3);

    scatter_all<<<CB0 + CB1 + CB2 + CB3, 256>>>(src0, dst0, cur0, ss0,
                                                src1, dst1, cur1, ss1,
                                                src2, dst2, cur2, ss2,
                                                src3, dst3, cur3, ss3);

    wsplit_all<<<57, 256>>>(convW, convB, ws, bcomb);

    GP zero{};

    // ===== layer 1 =====
    {
        GP pz0 = {h0_lt, nullptr, N_LT, ws0 + 0 * 8192, 4,
                  nullptr, nullptr, nullptr, nullptr, nullptr, z_lt};
        GP pz1 = {h0_cm, nullptr, N_CM, ws0 + 4 * 8192, 4,
                  nullptr, nullptr, nullptr, nullptr, nullptr, z_cm};
        gemm3_kernel<<<GB_LT + GB_CM, 256>>>(pz0, pz1, pz1, GB_LT, GB_CM);

        csr_all_kernel<<<(CSR_WARPS * 32 + 255) / 256, 256>>>(
            rp0, ss0, z_lt, rp1, ss1, z_cm, mean_bv,
            rp2, ss2, h0_dn, agg2, lnb + 384, 0,
            rp3, ss3, h0_bv, agg3);

        GP pb = {h0_bv, nullptr, N_BV, ws0 + 8 * 8192, 4,
                 bcomb + 0, mean_bv, bias_bv, lng + 0, lnb + 0, HBV};
        GP pl = {h0_lt, agg2, N_LT, ws0 + 12 * 8192, 8,
                 convB + 2 * 128, bias_lt, nullptr, lng + 128, lnb + 128, HLT};
        GP pc = {h0_cm, agg3, N_CM, ws0 + 20 * 8192, 8,
                 convB + 3 * 128, bias_cm, nullptr, lng + 256, lnb + 256, HCM};
        gemm3_kernel<<<GB_BV + GB_LT + GB_CM, 256>>>(pb, pl, pc, GB_BV, GB_LT);
    }

    // ===== layer 2 =====
    {
        GP pz0 = {HLT, nullptr, N_LT, ws1 + 0 * 8192, 4,
                  nullptr, nullptr, nullptr, nullptr, nullptr, z_lt};
        GP pz1 = {HCM, nullptr, N_CM, ws1 + 4 * 8192, 4,
                  nullptr, nullptr, nullptr, nullptr, nullptr, z_cm};
        gemm3_kernel<<<GB_LT + GB_CM, 256>>>(pz0, pz1, pz1, GB_LT, GB_CM);

        csr_all_kernel<<<(CSR_WARPS * 32 + 255) / 256, 256>>>(
            rp0, ss0, z_lt, rp1, ss1, z_cm, mean_bv,
            rp2, ss2, nullptr, agg2, lnb + 384, 1,
            rp3, ss3, HBV, agg3);

        GP pb = {HBV, nullptr, N_BV, ws1 + 8 * 8192, 4,
                 bcomb + 128, mean_bv, bias_bv, lng + 0, lnb + 0, out_bv};
        GP pl = {HLT, agg2, N_LT, ws1 + 12 * 8192, 8,
                 convB + 6 * 128, bias_lt, nullptr, lng + 128, lnb + 128, out_lt};
        GP pc = {HCM, agg3, N_CM, ws1 + 20 * 8192, 8,
                 convB + 7 * 128, bias_cm, nullptr, lng + 256, lnb + 256, out_cm};
        gemm3_kernel<<<GB_BV + GB_LT + GB_CM, 256>>>(pb, pl, pc, GB_BV, GB_LT);
    }
    (void)zero;
}